// round 13
// baseline (speedup 1.0000x reference)
#include <cuda_runtime.h>
#include <cuda_bf16.h>
#include <cuda_fp16.h>
#include <cstdint>
#include <math.h>

#define B_ 4
#define T_ 1024
#define H_ 512
#define P_ 20
#define V_ 32000
#define BT (B_*T_)
#define NB1 128

typedef __nv_bfloat16 bf16;

// ---------------- scratch (device globals) ----------------
__device__ __align__(256) float g_xw[BT*2048];
__device__ __align__(256) float g_enc[BT*512];
__device__ __align__(256) float g_pxw[BT*128];
__device__ float g_mu[BT];
__device__ float g_sig[BT];
__device__ __align__(128) unsigned g_flags[128];
__device__ float g_bp[128];

__device__ __align__(256) bf16 g_emb_hi[V_*H_];
__device__ __align__(256) bf16 g_emb_lo[V_*H_];
__device__ __align__(256) __half g_emb_f[V_*H_];
__device__ __align__(256) bf16 g_wih_hi[4*H_*H_];
__device__ __align__(256) bf16 g_wih_lo[4*H_*H_];
__device__ __align__(256) bf16 g_x_hi[BT*H_];
__device__ __align__(256) bf16 g_x_lo[BT*H_];
__device__ __align__(256) bf16 g_enc_hi[BT*H_];
__device__ __align__(256) bf16 g_enc_lo[BT*H_];
__device__ __align__(256) bf16 g_et_hi[B_*H_*T_];
__device__ __align__(256) bf16 g_et_lo[B_*H_*T_];
__device__ __align__(256) bf16 g_w_hi[B_*T_*T_];
__device__ __align__(256) bf16 g_w_lo[B_*T_*T_];
__device__ __align__(256) bf16 g_ctx_hi[BT*H_];
__device__ __align__(256) bf16 g_ctx_lo[BT*H_];
__device__ __align__(256) __half g_comb_fh[BT*H_];
__device__ __align__(256) __half g_comb_fl[BT*H_];
__device__ __align__(256) bf16 g_wc_hi[H_*2*H_];
__device__ __align__(256) bf16 g_wc_lo[H_*2*H_];
__device__ __align__(256) bf16 g_wp_hi[128*H_];
__device__ __align__(256) bf16 g_wp_lo[128*H_];

__device__ __forceinline__ float sigf(float x) { return 1.f / (1.f + __expf(-x)); }
__device__ __forceinline__ float tfast(float x) {
    float a = fabsf(x);
    float e = __expf(2.f * a);
    float t = 1.f - 2.f / (1.f + e);
    return copysignf(t, x);
}

__device__ __forceinline__ uint32_t smem_u32(const void* p) {
    uint32_t a;
    asm("{ .reg .u64 t; cvta.to.shared.u64 t, %1; cvt.u32.u64 %0, t; }"
        : "=r"(a) : "l"(p));
    return a;
}

#define CP_ASYNC16(s, g) \
    asm volatile("cp.async.cg.shared.global [%0], [%1], 16;" :: "r"(s), "l"(g))
#define CP_COMMIT() asm volatile("cp.async.commit_group;" ::: "memory")
#define CP_WAIT1()  asm volatile("cp.async.wait_group 1;" ::: "memory")
#define CP_WAIT0()  asm volatile("cp.async.wait_group 0;" ::: "memory")

#define LDSM4(r0, r1, r2, r3, a)                                             \
    asm volatile("ldmatrix.sync.aligned.m8n8.x4.shared.b16 {%0,%1,%2,%3}, [%4];" \
        : "=r"(r0), "=r"(r1), "=r"(r2), "=r"(r3) : "r"(a))

#define MMA16816(c, A0, A1, A2, A3, B0, B1)                                  \
    asm volatile("mma.sync.aligned.m16n8k16.row.col.f32.bf16.bf16.f32 "      \
        "{%0,%1,%2,%3}, {%4,%5,%6,%7}, {%8,%9}, {%0,%1,%2,%3};"              \
        : "+f"((c)[0]), "+f"((c)[1]), "+f"((c)[2]), "+f"((c)[3])             \
        : "r"(A0), "r"(A1), "r"(A2), "r"(A3), "r"(B0), "r"(B1))

#define MMAF16(c, A0, A1, A2, A3, B0, B1)                                    \
    asm volatile("mma.sync.aligned.m16n8k16.row.col.f32.f16.f16.f32 "        \
        "{%0,%1,%2,%3}, {%4,%5,%6,%7}, {%8,%9}, {%0,%1,%2,%3};"              \
        : "+f"((c)[0]), "+f"((c)[1]), "+f"((c)[2]), "+f"((c)[3])             \
        : "r"(A0), "r"(A1), "r"(A2), "r"(A3), "r"(B0), "r"(B1))

// ---------------- split fp32 -> bf16 hi/lo (+ optional fp16) ----------------
__global__ void k_split(const float* __restrict__ src,
                        bf16* __restrict__ hi, bf16* __restrict__ lo,
                        __half* __restrict__ fh, int n)
{
    int i = blockIdx.x * blockDim.x + threadIdx.x;
    if (i < n) {
        float v = src[i];
        bf16 h = __float2bfloat16(v);
        hi[i] = h;
        lo[i] = __float2bfloat16(v - __bfloat162float(h));
        if (fh) fh[i] = __float2half(v);
    }
}

__global__ void k_padbias(const float* __restrict__ b1, const float* __restrict__ b2)
{
    int i = threadIdx.x;
    if (i < 80) g_bp[i] = b1[i] + b2[i];
}

// ---------------- embedding gather + flag reset ----------------
__global__ void k_embed_bf(const int* __restrict__ ids)
{
    if (blockIdx.x == 0 && threadIdx.x < 128) g_flags[threadIdx.x] = 0;
    int i = blockIdx.x * blockDim.x + threadIdx.x;
    if (i < BT * H_) {
        int bt = i >> 9;
        int h  = i & 511;
        size_t src = (size_t)ids[bt] * H_ + h;
        g_x_hi[i] = g_emb_hi[src];
        g_x_lo[i] = g_emb_lo[src];
    }
}

// ---------------- generalized bf16x3 HMMA GEMM, 2-stage cp.async (proven) --------
#define MMA_SMEM (2 * 65536)

__global__ __launch_bounds__(256)
void k_mma(const bf16* __restrict__ Ah1, const bf16* __restrict__ Al1, int lda1,
           const bf16* __restrict__ Ah2, const bf16* __restrict__ Al2, int lda2,
           int ksplit, int nchunks, int mbpb, size_t sAbat,
           const bf16* __restrict__ Bh, const bf16* __restrict__ Bl, int ldb, size_t sBbat,
           int N, const float* __restrict__ bias1, const float* __restrict__ bias2,
           float* __restrict__ Cf, bf16* __restrict__ Chi, bf16* __restrict__ Clo,
           int actTanh, int tri, int outHalf)
{
    extern __shared__ char dsm[];
    const uint32_t ub = smem_u32(dsm);
    const int tid = threadIdx.x, lane = tid & 31, wid = tid >> 5;
    const int bm = blockIdx.y, bn = blockIdx.x;
    const int bq = bm / mbpb;
    const int am0 = (bm - bq * mbpb) * 128;
    const bf16* A1h = Ah1 + (size_t)bq * sAbat;
    const bf16* A1l = Al1 + (size_t)bq * sAbat;
    const bf16* Bbh = Bh + (size_t)bq * sBbat;
    const bf16* Bbl = Bl + (size_t)bq * sBbat;

    if (tri) { int need = (am0 >> 6) + 2; if (need < nchunks) nchunks = need; }

    const int wm = (wid >> 2) * 64, wn = (wid & 3) * 32;
    const int aRow = lane & 15, aGrp = lane >> 4;
    const int bRow = (lane & 7) + ((lane >> 4) << 3), bGrp = (lane >> 3) & 1;

    auto issue = [&](int c, int st) {
        uint32_t sb = ub + st * 65536;
#pragma unroll
        for (int i = 0; i < 4; ++i) {
            int idx = i * 256 + tid;
            int row = idx >> 3, seg = idx & 7;
            uint32_t so = sb + (uint32_t)(row * 128 + ((seg ^ (row & 7)) << 4));
            const bf16 *pah, *pal;
            if (c < ksplit) {
                size_t o = (size_t)(am0 + row) * lda1 + c * 64 + seg * 8;
                pah = A1h + o; pal = A1l + o;
            } else {
                size_t o = (size_t)(am0 + row) * lda2 + (c - ksplit) * 64 + seg * 8;
                pah = Ah2 + o; pal = Al2 + o;
            }
            size_t ob = (size_t)(bn * 128 + row) * ldb + c * 64 + seg * 8;
            CP_ASYNC16(so,         pah);
            CP_ASYNC16(so + 16384, pal);
            CP_ASYNC16(so + 32768, Bbh + ob);
            CP_ASYNC16(so + 49152, Bbl + ob);
        }
        CP_COMMIT();
    };

    float acc[4][4][4];
#pragma unroll
    for (int i = 0; i < 4; i++)
#pragma unroll
        for (int j = 0; j < 4; j++)
#pragma unroll
            for (int q = 0; q < 4; q++) acc[i][j][q] = 0.f;

    issue(0, 0);
    for (int c = 0; c < nchunks; ++c) {
        if (c + 1 < nchunks) { issue(c + 1, (c + 1) & 1); CP_WAIT1(); }
        else CP_WAIT0();
        __syncthreads();

        uint32_t uAh = ub + (c & 1) * 65536;
        uint32_t uAl = uAh + 16384, uBh = uAh + 32768, uBl = uAh + 49152;
#pragma unroll
        for (int ks = 0; ks < 4; ++ks) {
            uint32_t bh[8], bl[8];
#pragma unroll
            for (int h = 0; h < 2; ++h) {
                int row = wn + h * 16 + bRow;
                int grp = 2 * ks + bGrp;
                uint32_t off = (uint32_t)(row * 128 + ((grp ^ (row & 7)) << 4));
                LDSM4(bh[h*4+0], bh[h*4+1], bh[h*4+2], bh[h*4+3], uBh + off);
                LDSM4(bl[h*4+0], bl[h*4+1], bl[h*4+2], bl[h*4+3], uBl + off);
            }
#pragma unroll
            for (int mi = 0; mi < 4; ++mi) {
                int row = wm + mi * 16 + aRow;
                int grp = 2 * ks + aGrp;
                uint32_t off = (uint32_t)(row * 128 + ((grp ^ (row & 7)) << 4));
                uint32_t ah[4], al[4];
                LDSM4(ah[0], ah[1], ah[2], ah[3], uAh + off);
                LDSM4(al[0], al[1], al[2], al[3], uAl + off);
#pragma unroll
                for (int ni = 0; ni < 4; ++ni) {
                    int bx = (ni >> 1) * 4 + (ni & 1) * 2;
                    MMA16816(acc[mi][ni], ah[0], ah[1], ah[2], ah[3], bh[bx], bh[bx+1]);
                    MMA16816(acc[mi][ni], ah[0], ah[1], ah[2], ah[3], bl[bx], bl[bx+1]);
                    MMA16816(acc[mi][ni], al[0], al[1], al[2], al[3], bh[bx], bh[bx+1]);
                }
            }
        }
        __syncthreads();
    }

    // epilogue
#pragma unroll
    for (int mi = 0; mi < 4; ++mi) {
#pragma unroll
        for (int ni = 0; ni < 4; ++ni) {
            int row = bm * 128 + wm + mi * 16 + (lane >> 2);
            int col = bn * 128 + wn + ni * 8 + ((lane & 3) << 1);
            float b0 = 0.f, b1 = 0.f;
            if (bias1) { b0 = bias1[col]; b1 = bias1[col + 1]; }
            if (bias2) { b0 += bias2[col]; b1 += bias2[col + 1]; }
            float v00 = acc[mi][ni][0] + b0, v01 = acc[mi][ni][1] + b1;
            float v10 = acc[mi][ni][2] + b0, v11 = acc[mi][ni][3] + b1;
            if (actTanh) {
                v00 = tfast(v00); v01 = tfast(v01);
                v10 = tfast(v10); v11 = tfast(v11);
            }
            size_t i0 = (size_t)row * N + col;
            size_t i1 = (size_t)(row + 8) * N + col;
            if (Cf) {
                *(float2*)&Cf[i0] = make_float2(v00, v01);
                *(float2*)&Cf[i1] = make_float2(v10, v11);
            }
            if (Chi) {
                if (outHalf) {
                    __half* H = (__half*)Chi;
                    __half* L = (__half*)Clo;
                    __half h00 = __float2half(v00), h01 = __float2half(v01);
                    __half h10 = __float2half(v10), h11 = __float2half(v11);
                    __half2 p;
                    p.x = h00; p.y = h01; *(__half2*)&H[i0] = p;
                    p.x = h10; p.y = h11; *(__half2*)&H[i1] = p;
                    p.x = __float2half(v00 - __half2float(h00));
                    p.y = __float2half(v01 - __half2float(h01));
                    *(__half2*)&L[i0] = p;
                    p.x = __float2half(v10 - __half2float(h10));
                    p.y = __float2half(v11 - __half2float(h11));
                    *(__half2*)&L[i1] = p;
                } else {
                    bf16 h00 = __float2bfloat16(v00), h01 = __float2bfloat16(v01);
                    bf16 h10 = __float2bfloat16(v10), h11 = __float2bfloat16(v11);
                    __nv_bfloat162 p;
                    p.x = h00; p.y = h01; *(__nv_bfloat162*)&Chi[i0] = p;
                    p.x = h10; p.y = h11; *(__nv_bfloat162*)&Chi[i1] = p;
                    p.x = __float2bfloat16(v00 - __bfloat162float(h00));
                    p.y = __float2bfloat16(v01 - __bfloat162float(h01));
                    *(__nv_bfloat162*)&Clo[i0] = p;
                    p.x = __float2bfloat16(v10 - __bfloat162float(h10));
                    p.y = __float2bfloat16(v11 - __bfloat162float(h11));
                    *(__nv_bfloat162*)&Clo[i1] = p;
                }
            }
        }
    }
}

// ---------------- K7 decoder: fp16 2-term GEMM (A=2-term, B=hi only) ----------------
// grid=(Mtiles=32, Ntiles=250), bm fastest: A (4MB) L2-resident, emb streamed once.
#define MMA7_SMEM (2 * 49152)

__global__ __launch_bounds__(256)
void k_mma7(const __half* __restrict__ Ah, const __half* __restrict__ Al,
            const __half* __restrict__ Bh, int N,
            const float* __restrict__ bias, float* __restrict__ Cf)
{
    extern __shared__ char dsm[];
    const uint32_t ub = smem_u32(dsm);
    const int tid = threadIdx.x, lane = tid & 31, wid = tid >> 5;
    const int bm = blockIdx.x, bn = blockIdx.y;
    const int wm = (wid >> 2) * 64, wn = (wid & 3) * 32;
    const int aRow = lane & 15, aGrp = lane >> 4;
    const int bRow = (lane & 7) + ((lane >> 4) << 3), bGrp = (lane >> 3) & 1;

    auto issue = [&](int c, int st) {
        uint32_t sb = ub + st * 49152;
#pragma unroll
        for (int i = 0; i < 4; ++i) {
            int idx = i * 256 + tid;
            int row = idx >> 3, seg = idx & 7;
            uint32_t so = sb + (uint32_t)(row * 128 + ((seg ^ (row & 7)) << 4));
            size_t oa = (size_t)(bm * 128 + row) * 512 + c * 64 + seg * 8;
            size_t ob = (size_t)(bn * 128 + row) * 512 + c * 64 + seg * 8;
            CP_ASYNC16(so,         Ah + oa);
            CP_ASYNC16(so + 16384, Al + oa);
            CP_ASYNC16(so + 32768, Bh + ob);
        }
        CP_COMMIT();
    };

    float acc[4][4][4];
#pragma unroll
    for (int i = 0; i < 4; i++)
#pragma unroll
        for (int j = 0; j < 4; j++)
#pragma unroll
            for (int q = 0; q < 4; q++) acc[i][j][q] = 0.f;

    issue(0, 0);
    for (int c = 0; c < 8; ++c) {
        if (c + 1 < 8) { issue(c + 1, (c + 1) & 1); CP_WAIT1(); }
        else CP_WAIT0();
        __syncthreads();

        uint32_t uA = ub + (c & 1) * 49152;
        uint32_t uAl = uA + 16384, uB = uA + 32768;
#pragma unroll
        for (int ks = 0; ks < 4; ++ks) {
            uint32_t bh[8];
#pragma unroll
            for (int h = 0; h < 2; ++h) {
                int row = wn + h * 16 + bRow;
                int grp = 2 * ks + bGrp;
                uint32_t off = (uint32_t)(row * 128 + ((grp ^ (row & 7)) << 4));
                LDSM4(bh[h*4+0], bh[h*4+1], bh[h*4+2], bh[h*4+3], uB + off);
            }
#pragma unroll
            for (int mi = 0; mi < 4; ++mi) {
                int row = wm + mi * 16 + aRow;
                int grp = 2 * ks + aGrp;
                uint32_t off = (uint32_t)(row * 128 + ((grp ^ (row & 7)) << 4));
                uint32_t ah[4], al[4];
                LDSM4(ah[0], ah[1], ah[2], ah[3], uA + off);
                LDSM4(al[0], al[1], al[2], al[3], uAl + off);
#pragma unroll
                for (int ni = 0; ni < 4; ++ni) {
                    int bx = (ni >> 1) * 4 + (ni & 1) * 2;
                    MMAF16(acc[mi][ni], ah[0], ah[1], ah[2], ah[3], bh[bx], bh[bx+1]);
                    MMAF16(acc[mi][ni], al[0], al[1], al[2], al[3], bh[bx], bh[bx+1]);
                }
            }
        }
        __syncthreads();
    }

#pragma unroll
    for (int mi = 0; mi < 4; ++mi) {
#pragma unroll
        for (int ni = 0; ni < 4; ++ni) {
            int row = bm * 128 + wm + mi * 16 + (lane >> 2);
            int col = bn * 128 + wn + ni * 8 + ((lane & 3) << 1);
            float b0 = bias[col], b1 = bias[col + 1];
            size_t i0 = (size_t)row * N + col;
            size_t i1 = (size_t)(row + 8) * N + col;
            *(float2*)&Cf[i0] = make_float2(acc[mi][ni][0] + b0, acc[mi][ni][1] + b1);
            *(float2*)&Cf[i1] = make_float2(acc[mi][ni][2] + b0, acc[mi][ni][3] + b1);
        }
    }
}

// ---------------- LSTM-1 persistent kernel (flag barrier) ----------------
__global__ __launch_bounds__(256)
void k_lstm1(const float* __restrict__ Whh)
{
    __shared__ float hsm[2048];
    __shared__ float gsum[64];
    __shared__ float csm[16];
    const int tid  = threadIdx.x;
    const int u0   = blockIdx.x * 4;
    const int warp = tid >> 5, lane = tid & 31;

    const int r0 = 2 * warp, r1 = 2 * warp + 1;
    const float* W0 = Whh + ((size_t)((r0 >> 2) * 512 + u0 + (r0 & 3))) * 512;
    const float* W1 = Whh + ((size_t)((r1 >> 2) * 512 + u0 + (r1 & 3))) * 512;
    float4 w0[4], w1[4];
#pragma unroll
    for (int q = 0; q < 4; ++q) {
        w0[q] = *(const float4*)(W0 + 4 * lane + 128 * q);
        w1[q] = *(const float4*)(W1 + 4 * lane + 128 * q);
    }
    if (tid < 16) csm[tid] = 0.f;
    __syncthreads();

    for (int t = 0; t < T_; ++t) {
        float xg[4];
        if (tid < 16) {
            int uu = tid >> 2, b = tid & 3;
            const float* xr = g_xw + (size_t)(b * T_ + t) * 2048 + u0 + uu;
            xg[0] = xr[0]; xg[1] = xr[512]; xg[2] = xr[1024]; xg[3] = xr[1536];
        }
        if (t > 0) {
            for (int i = tid; i < 512; i += 256) {
                int b = i >> 7, k4 = i & 127;
                ((float4*)hsm)[i] =
                    ((const float4*)(g_enc + (size_t)(b * T_ + t - 1) * 512))[k4];
            }
        } else {
            for (int i = tid; i < 2048; i += 256) hsm[i] = 0.f;
        }
        __syncthreads();

        float s[8];
#pragma unroll
        for (int b = 0; b < 4; ++b) {
            const float* hb = hsm + b * 512 + 4 * lane;
            float4 h0 = *(const float4*)(hb);
            float4 h1 = *(const float4*)(hb + 128);
            float4 h2 = *(const float4*)(hb + 256);
            float4 h3 = *(const float4*)(hb + 384);
            float a0, a1;
            a0 = w0[0].x*h0.x + w0[0].y*h0.y + w0[0].z*h0.z + w0[0].w*h0.w;
            a0 += w0[1].x*h1.x + w0[1].y*h1.y + w0[1].z*h1.z + w0[1].w*h1.w;
            a0 += w0[2].x*h2.x + w0[2].y*h2.y + w0[2].z*h2.z + w0[2].w*h2.w;
            a0 += w0[3].x*h3.x + w0[3].y*h3.y + w0[3].z*h3.z + w0[3].w*h3.w;
            a1 = w1[0].x*h0.x + w1[0].y*h0.y + w1[0].z*h0.z + w1[0].w*h0.w;
            a1 += w1[1].x*h1.x + w1[1].y*h1.y + w1[1].z*h1.z + w1[1].w*h1.w;
            a1 += w1[2].x*h2.x + w1[2].y*h2.y + w1[2].z*h2.z + w1[2].w*h2.w;
            a1 += w1[3].x*h3.x + w1[3].y*h3.y + w1[3].z*h3.z + w1[3].w*h3.w;
            s[b * 2] = a0; s[b * 2 + 1] = a1;
        }
#pragma unroll
        for (int i = 0; i < 8; ++i) {
            s[i] += __shfl_xor_sync(0xffffffffu, s[i], 16);
            s[i] += __shfl_xor_sync(0xffffffffu, s[i], 8);
            s[i] += __shfl_xor_sync(0xffffffffu, s[i], 4);
            s[i] += __shfl_xor_sync(0xffffffffu, s[i], 2);
            s[i] += __shfl_xor_sync(0xffffffffu, s[i], 1);
        }
        if (lane < 8) {
            float v = (lane < 4) ? s[2 * lane] : s[2 * (lane - 4) + 1];
            gsum[warp * 8 + lane] = v;
        }
        __syncthreads();

        if (tid < 16) {
            int uu = tid >> 2, bb = tid & 3;
            float gi = gsum[((0 * 4 + uu) << 2) | bb] + xg[0];
            float gf = gsum[((1 * 4 + uu) << 2) | bb] + xg[1];
            float gg = gsum[((2 * 4 + uu) << 2) | bb] + xg[2];
            float go = gsum[((3 * 4 + uu) << 2) | bb] + xg[3];
            float c = sigf(gf) * csm[tid] + sigf(gi) * tfast(gg);
            csm[tid] = c;
            float h = sigf(go) * tfast(c);
            int u  = u0 + uu;
            size_t bt = (size_t)(bb * T_ + t);
            g_enc[bt * 512 + u] = h;
            bf16 hh = __float2bfloat16(h);
            bf16 hl = __float2bfloat16(h - __bfloat162float(hh));
            g_enc_hi[bt * 512 + u] = hh;
            g_enc_lo[bt * 512 + u] = hl;
            size_t ei = ((size_t)bb * 512 + u) * 1024 + t;
            g_et_hi[ei] = hh;
            g_et_lo[ei] = hl;
            __threadfence();
        }
        __syncthreads();

        // flag barrier: publish arrival, then warp 0 polls all 128 flags
        if (tid == 0) *(volatile unsigned*)&g_flags[blockIdx.x] = (unsigned)(t + 1);
        if (warp == 0) {
            bool ok;
            do {
                unsigned v0 = *(volatile unsigned*)&g_flags[lane];
                unsigned v1 = *(volatile unsigned*)&g_flags[lane + 32];
                unsigned v2 = *(volatile unsigned*)&g_flags[lane + 64];
                unsigned v3 = *(volatile unsigned*)&g_flags[lane + 96];
                unsigned mn = min(min(v0, v1), min(v2, v3));
                ok = __all_sync(0xffffffffu, mn >= (unsigned)(t + 1));
            } while (!ok);
        }
        __syncthreads();
    }
}

// ---------------- LSTM-2: 4 independent warps ----------------
__global__ __launch_bounds__(128)
void k_lstm2(const float* __restrict__ Wp_hh,
             const float* __restrict__ Wmu, const float* __restrict__ bmu,
             const float* __restrict__ Wsig, const float* __restrict__ bsig,
             const int* __restrict__ pad)
{
    __shared__ float wp[1600];
    __shared__ float wmu_s[60];
    __shared__ float wsig_s[20];
    __shared__ float bconst[4];
    __shared__ float hp[4][20];
    __shared__ float gp[4][80];
    __shared__ float tmp[4][4];
    const int tid = threadIdx.x;
    const int b = tid >> 5, lane = tid & 31;

    for (int i = tid; i < 1600; i += 128) wp[i] = Wp_hh[i];
    for (int i = tid; i < 60; i += 128) wmu_s[i] = Wmu[i];
    if (tid < 20) wsig_s[tid] = Wsig[tid];
    if (tid < 3) bconst[tid] = bmu[tid];
    if (tid == 3) bconst[3] = bsig[0];
    if (tid < 80) hp[tid / 20][tid % 20] = 0.f;
    __syncthreads();

    const float invL = 1.f / (float)pad[b];
    float cc = 0.f;
    float mu_prev = 0.f;
    const int r0 = lane, r1 = lane + 32, r2 = lane + 64;
    const int r2c = (r2 < 80) ? r2 : 79;

    float px0 = g_pxw[(size_t)(b * T_) * 128 + r0];
    float px1 = g_pxw[(size_t)(b * T_) * 128 + r1];
    float px2 = (r2 < 80) ? g_pxw[(size_t)(b * T_) * 128 + r2] : 0.f;

    for (int t = 0; t < T_; ++t) {
        float s0 = px0, s1 = px1, s2 = px2;
#pragma unroll
        for (int k = 0; k < 20; ++k) {
            float h = hp[b][k];
            s0 = fmaf(wp[r0 * 20 + k], h, s0);
            s1 = fmaf(wp[r1 * 20 + k], h, s1);
            s2 = fmaf(wp[r2c * 20 + k], h, s2);
        }
        gp[b][r0] = s0;
        gp[b][r1] = s1;
        if (r2 < 80) gp[b][r2] = s2;
        if (t + 1 < T_) {
            size_t base = (size_t)(b * T_ + t + 1) * 128;
            px0 = g_pxw[base + r0];
            px1 = g_pxw[base + r1];
            if (r2 < 80) px2 = g_pxw[base + r2];
        }
        __syncwarp();
        if (lane < 20) {
            float gi = gp[b][lane], gf = gp[b][20 + lane];
            float gg = gp[b][40 + lane], go = gp[b][60 + lane];
            cc = sigf(gf) * cc + sigf(gi) * tfast(gg);
            hp[b][lane] = sigf(go) * tfast(cc);
        }
        __syncwarp();
        if (lane >= 20 && lane < 24) {
            int s = lane - 20;
            const float* wv = (s < 3) ? &wmu_s[s * 20] : wsig_s;
            float acc = bconst[s];
#pragma unroll
            for (int k = 0; k < 20; ++k) acc = fmaf(wv[k], hp[b][k], acc);
            tmp[b][s] = acc;
        }
        __syncwarp();
        if (lane == 0) {
            float m0 = fmaxf(tmp[b][0], 0.f);
            float m1 = fmaxf(tmp[b][1], 0.f);
            float m2 = fmaxf(tmp[b][2], 0.f);
            float sg = sigf(tmp[b][3]);
            float mu = fmaf(m0, mu_prev, (m1 + m2 * (float)(t + 1)) * invL);
            mu_prev = mu;
            g_mu[b * T_ + t]  = mu;
            g_sig[b * T_ + t] = sg;
        }
    }
}

// ---------------- attention weights: compute, normalize, split to bf16 ----------
__global__ __launch_bounds__(256)
void k_wnorm()
{
    __shared__ float wsm[1024];
    __shared__ float red[8];
    const int tid = threadIdx.x, lane = tid & 31, warp = tid >> 5;
    const int bj = blockIdx.x;
    const int b = bj >> 10, j = bj & 1023;
    const float mu = g_mu[bj];
    const float sg = g_sig[bj];
    const float invd  = 1.f / (2.f * sg * sg + 0.001f);
    const float invj1 = 1.f / (float)(j + 1);

    float lsum = 0.f;
#pragma unroll
    for (int i = 0; i < 4; ++i) {
        int t = tid + i * 256;
        float w = 0.f;
        if (t <= j) {
            float r = (float)t * invj1 - mu;
            w = __expf(-r * r * invd);
        }
        wsm[t] = w;
        lsum += w;
    }
    lsum += __shfl_xor_sync(0xffffffffu, lsum, 16);
    lsum += __shfl_xor_sync(0xffffffffu, lsum, 8);
    lsum += __shfl_xor_sync(0xffffffffu, lsum, 4);
    lsum += __shfl_xor_sync(0xffffffffu, lsum, 2);
    lsum += __shfl_xor_sync(0xffffffffu, lsum, 1);
    if (lane == 0) red[warp] = lsum;
    __syncthreads();
    float tot = red[0] + red[1] + red[2] + red[3] + red[4] + red[5] + red[6] + red[7];
    const float scale = 1.f / fmaxf(tot, 1e-12f);

    size_t base = ((size_t)b << 20) + ((size_t)j << 10);
#pragma unroll
    for (int i = 0; i < 4; ++i) {
        int t = tid + i * 256;
        float v = wsm[t] * scale;
        bf16 h = __float2bfloat16(v);
        g_w_hi[base + t] = h;
        g_w_lo[base + t] = __float2bfloat16(v - __bfloat162float(h));
    }
}

// ---------------- launch ----------------
extern "C" void kernel_launch(void* const* d_in, const int* in_sizes, int n_in,
                              void* d_out, int out_size)
{
    const int*   ids      = (const int*)d_in[0];
    const int*   pad      = (const int*)d_in[1];
    const float* emb      = (const float*)d_in[2];
    const float* dec_bias = (const float*)d_in[3];
    const float* Wih      = (const float*)d_in[4];
    const float* Whh      = (const float*)d_in[5];
    const float* bih      = (const float*)d_in[6];
    const float* bhh      = (const float*)d_in[7];
    const float* Wp_ih    = (const float*)d_in[8];
    const float* Wp_hh    = (const float*)d_in[9];
    const float* bp_ih    = (const float*)d_in[10];
    const float* bp_hh    = (const float*)d_in[11];
    const float* Wmu      = (const float*)d_in[12];
    const float* bmu      = (const float*)d_in[13];
    const float* Wsig     = (const float*)d_in[14];
    const float* bsig     = (const float*)d_in[15];
    const float* Wc       = (const float*)d_in[16];
    const float* bc       = (const float*)d_in[17];
    float* out = (float*)d_out;

    float *p_xw, *p_pxw, *p_bp;
    bf16 *p_ehi, *p_elo, *p_whi, *p_wlo, *p_xhi, *p_xlo;
    bf16 *p_nhi, *p_nlo, *p_ethi, *p_etlo, *p_awhi, *p_awlo;
    bf16 *p_cxhi, *p_cxlo, *p_wchi, *p_wclo, *p_wphi, *p_wplo;
    __half *p_ef, *p_cfh, *p_cfl;
    cudaGetSymbolAddress((void**)&p_xw,    g_xw);
    cudaGetSymbolAddress((void**)&p_pxw,   g_pxw);
    cudaGetSymbolAddress((void**)&p_bp,    g_bp);
    cudaGetSymbolAddress((void**)&p_ehi,   g_emb_hi);
    cudaGetSymbolAddress((void**)&p_elo,   g_emb_lo);
    cudaGetSymbolAddress((void**)&p_ef,    g_emb_f);
    cudaGetSymbolAddress((void**)&p_whi,   g_wih_hi);
    cudaGetSymbolAddress((void**)&p_wlo,   g_wih_lo);
    cudaGetSymbolAddress((void**)&p_xhi,   g_x_hi);
    cudaGetSymbolAddress((void**)&p_xlo,   g_x_lo);
    cudaGetSymbolAddress((void**)&p_nhi,   g_enc_hi);
    cudaGetSymbolAddress((void**)&p_nlo,   g_enc_lo);
    cudaGetSymbolAddress((void**)&p_ethi,  g_et_hi);
    cudaGetSymbolAddress((void**)&p_etlo,  g_et_lo);
    cudaGetSymbolAddress((void**)&p_awhi,  g_w_hi);
    cudaGetSymbolAddress((void**)&p_awlo,  g_w_lo);
    cudaGetSymbolAddress((void**)&p_cxhi,  g_ctx_hi);
    cudaGetSymbolAddress((void**)&p_cxlo,  g_ctx_lo);
    cudaGetSymbolAddress((void**)&p_cfh,   g_comb_fh);
    cudaGetSymbolAddress((void**)&p_cfl,   g_comb_fl);
    cudaGetSymbolAddress((void**)&p_wchi,  g_wc_hi);
    cudaGetSymbolAddress((void**)&p_wclo,  g_wc_lo);
    cudaGetSymbolAddress((void**)&p_wphi,  g_wp_hi);
    cudaGetSymbolAddress((void**)&p_wplo,  g_wp_lo);

    cudaFuncSetAttribute(k_mma, cudaFuncAttributeMaxDynamicSharedMemorySize, MMA_SMEM);
    cudaFuncSetAttribute(k_mma7, cudaFuncAttributeMaxDynamicSharedMemorySize, MMA7_SMEM);

    const int NOB = 1 << 28;

    k_split<<<(V_ * H_ + 255) / 256, 256>>>(emb, p_ehi, p_elo, p_ef, V_ * H_);
    k_split<<<(4 * H_ * H_ + 255) / 256, 256>>>(Wih, p_whi, p_wlo, nullptr, 4 * H_ * H_);
    k_split<<<(H_ * 2 * H_ + 255) / 256, 256>>>(Wc, p_wchi, p_wclo, nullptr, H_ * 2 * H_);
    k_split<<<(80 * H_ + 255) / 256, 256>>>(Wp_ih, p_wphi, p_wplo, nullptr, 80 * H_);
    k_padbias<<<1, 128>>>(bp_ih, bp_hh);
    k_embed_bf<<<(BT * H_ + 255) / 256, 256>>>(ids);

    // K1: xw = x @ Wih^T + bih + bhh -> fp32 [4096, 2048]
    k_mma<<<dim3(16, 32), 256, MMA_SMEM>>>(
        p_xhi, p_xlo, 512, nullptr, nullptr, 0, 8, 8, NOB, 0,
        p_whi, p_wlo, 512, 0, 2048, bih, bhh, p_xw, nullptr, nullptr, 0, 0, 0);

    // K2: LSTM-1 recurrence
    k_lstm1<<<NB1, 256>>>(Whh);

    // K3: pxw = enc @ Wp_ih^T + biases -> fp32 [4096, 128pad]
    k_mma<<<dim3(1, 32), 256, MMA_SMEM>>>(
        p_nhi, p_nlo, 512, nullptr, nullptr, 0, 8, 8, NOB, 0,
        p_wphi, p_wplo, 512, 0, 128, p_bp, nullptr, p_pxw, nullptr, nullptr, 0, 0, 0);

    // K4: LSTM-2 + mu/sigma scan
    k_lstm2<<<1, 128>>>(Wp_hh, Wmu, bmu, Wsig, bsig, pad);

    // K5a: attention weights
    k_wnorm<<<BT, 256>>>();

    // K5b: ctx = w @ enc (batched, triangular skip) -> bf16 hi/lo
    k_mma<<<dim3(4, 32), 256, MMA_SMEM>>>(
        p_awhi, p_awlo, 1024, nullptr, nullptr, 0, 16, 16, 8, (size_t)T_ * T_,
        p_ethi, p_etlo, 1024, (size_t)H_ * T_, 512,
        nullptr, nullptr, nullptr, p_cxhi, p_cxlo, 0, 1, 0);

    // K6: combined = tanh([ctx, enc] @ Wc^T + bc) -> fp16 hi/lo (for K7)
    k_mma<<<dim3(4, 32), 256, MMA_SMEM>>>(
        p_cxhi, p_cxlo, 512, p_nhi, p_nlo, 512, 8, 16, NOB, 0,
        p_wchi, p_wclo, 1024, 0, 512, bc, nullptr,
        nullptr, (bf16*)p_cfh, (bf16*)p_cfl, 1, 0, 1);

    // K7: logits = combined @ emb^T + dec_bias -> fp32 (fp16 2-term, bm-fastest grid)
    k_mma7<<<dim3(32, 250), 256, MMA7_SMEM>>>(
        p_cfh, p_cfl, p_ef, V_, dec_bias, out);
}

// round 14
// speedup vs baseline: 2.3376x; 2.3376x over previous
#include <cuda_runtime.h>
#include <cuda_bf16.h>
#include <cuda_fp16.h>
#include <cstdint>
#include <math.h>

#define B_ 4
#define T_ 1024
#define H_ 512
#define P_ 20
#define V_ 32000
#define BT (B_*T_)
#define NB1 128

typedef __nv_bfloat16 bf16;

// ---------------- scratch (device globals) ----------------
__device__ __align__(256) float g_xw[BT*2048];
__device__ __align__(256) float g_enc[BT*512];
__device__ __align__(256) float g_pxw[BT*128];
__device__ float g_mu[BT];
__device__ float g_sig[BT];
__device__ unsigned g_cnt[256];
__device__ unsigned g_root;
__device__ float g_bp[128];

__device__ __align__(256) bf16 g_emb_hi[V_*H_];
__device__ __align__(256) bf16 g_emb_lo[V_*H_];
__device__ __align__(256) __half g_emb_f[V_*H_];
__device__ __align__(256) bf16 g_wih_hi[4*H_*H_];
__device__ __align__(256) bf16 g_wih_lo[4*H_*H_];
__device__ __align__(256) bf16 g_x_hi[BT*H_];
__device__ __align__(256) bf16 g_x_lo[BT*H_];
__device__ __align__(256) bf16 g_enc_hi[BT*H_];
__device__ __align__(256) bf16 g_enc_lo[BT*H_];
__device__ __align__(256) bf16 g_et_hi[B_*H_*T_];
__device__ __align__(256) bf16 g_et_lo[B_*H_*T_];
__device__ __align__(256) bf16 g_w_hi[B_*T_*T_];
__device__ __align__(256) bf16 g_w_lo[B_*T_*T_];
__device__ __align__(256) bf16 g_ctx_hi[BT*H_];
__device__ __align__(256) bf16 g_ctx_lo[BT*H_];
__device__ __align__(256) __half g_comb_fh[BT*H_];
__device__ __align__(256) __half g_comb_fl[BT*H_];
__device__ __align__(256) bf16 g_wc_hi[H_*2*H_];
__device__ __align__(256) bf16 g_wc_lo[H_*2*H_];
__device__ __align__(256) bf16 g_wp_hi[128*H_];
__device__ __align__(256) bf16 g_wp_lo[128*H_];

__device__ __forceinline__ float sigf(float x) { return 1.f / (1.f + __expf(-x)); }
__device__ __forceinline__ float tfast(float x) {
    float a = fabsf(x);
    float e = __expf(2.f * a);
    float t = 1.f - 2.f / (1.f + e);
    return copysignf(t, x);
}

__device__ __forceinline__ uint32_t smem_u32(const void* p) {
    uint32_t a;
    asm("{ .reg .u64 t; cvta.to.shared.u64 t, %1; cvt.u32.u64 %0, t; }"
        : "=r"(a) : "l"(p));
    return a;
}

#define CP_ASYNC16(s, g) \
    asm volatile("cp.async.cg.shared.global [%0], [%1], 16;" :: "r"(s), "l"(g))
#define CP_COMMIT() asm volatile("cp.async.commit_group;" ::: "memory")
#define CP_WAIT1()  asm volatile("cp.async.wait_group 1;" ::: "memory")
#define CP_WAIT0()  asm volatile("cp.async.wait_group 0;" ::: "memory")

#define LDSM4(r0, r1, r2, r3, a)                                             \
    asm volatile("ldmatrix.sync.aligned.m8n8.x4.shared.b16 {%0,%1,%2,%3}, [%4];" \
        : "=r"(r0), "=r"(r1), "=r"(r2), "=r"(r3) : "r"(a))

#define MMA16816(c, A0, A1, A2, A3, B0, B1)                                  \
    asm volatile("mma.sync.aligned.m16n8k16.row.col.f32.bf16.bf16.f32 "      \
        "{%0,%1,%2,%3}, {%4,%5,%6,%7}, {%8,%9}, {%0,%1,%2,%3};"              \
        : "+f"((c)[0]), "+f"((c)[1]), "+f"((c)[2]), "+f"((c)[3])             \
        : "r"(A0), "r"(A1), "r"(A2), "r"(A3), "r"(B0), "r"(B1))

#define MMAF16(c, A0, A1, A2, A3, B0, B1)                                    \
    asm volatile("mma.sync.aligned.m16n8k16.row.col.f32.f16.f16.f32 "        \
        "{%0,%1,%2,%3}, {%4,%5,%6,%7}, {%8,%9}, {%0,%1,%2,%3};"              \
        : "+f"((c)[0]), "+f"((c)[1]), "+f"((c)[2]), "+f"((c)[3])             \
        : "r"(A0), "r"(A1), "r"(A2), "r"(A3), "r"(B0), "r"(B1))

// ---------------- split fp32 -> bf16 hi/lo (+ optional fp16) ----------------
__global__ void k_split(const float* __restrict__ src,
                        bf16* __restrict__ hi, bf16* __restrict__ lo,
                        __half* __restrict__ fh, int n)
{
    int i = blockIdx.x * blockDim.x + threadIdx.x;
    if (i < n) {
        float v = src[i];
        bf16 h = __float2bfloat16(v);
        hi[i] = h;
        lo[i] = __float2bfloat16(v - __bfloat162float(h));
        if (fh) fh[i] = __float2half(v);
    }
}

__global__ void k_padbias(const float* __restrict__ b1, const float* __restrict__ b2)
{
    int i = threadIdx.x;
    if (i < 80) g_bp[i] = b1[i] + b2[i];
}

// ---------------- embedding gather + barrier counter reset ----------------
__global__ void k_embed_bf(const int* __restrict__ ids)
{
    if (blockIdx.x == 0) {
        if (threadIdx.x == 0) g_root = 0;
        if (threadIdx.x < 8) g_cnt[threadIdx.x * 32] = 0;
    }
    int i = blockIdx.x * blockDim.x + threadIdx.x;
    if (i < BT * H_) {
        int bt = i >> 9;
        int h  = i & 511;
        size_t src = (size_t)ids[bt] * H_ + h;
        g_x_hi[i] = g_emb_hi[src];
        g_x_lo[i] = g_emb_lo[src];
    }
}

// ---------------- generalized bf16x3 HMMA GEMM, 2-stage cp.async (proven) --------
#define MMA_SMEM (2 * 65536)

__global__ __launch_bounds__(256)
void k_mma(const bf16* __restrict__ Ah1, const bf16* __restrict__ Al1, int lda1,
           const bf16* __restrict__ Ah2, const bf16* __restrict__ Al2, int lda2,
           int ksplit, int nchunks, int mbpb, size_t sAbat,
           const bf16* __restrict__ Bh, const bf16* __restrict__ Bl, int ldb, size_t sBbat,
           int N, const float* __restrict__ bias1, const float* __restrict__ bias2,
           float* __restrict__ Cf, bf16* __restrict__ Chi, bf16* __restrict__ Clo,
           int actTanh, int tri, int outHalf)
{
    extern __shared__ char dsm[];
    const uint32_t ub = smem_u32(dsm);
    const int tid = threadIdx.x, lane = tid & 31, wid = tid >> 5;
    const int bm = blockIdx.y, bn = blockIdx.x;
    const int bq = bm / mbpb;
    const int am0 = (bm - bq * mbpb) * 128;
    const bf16* A1h = Ah1 + (size_t)bq * sAbat;
    const bf16* A1l = Al1 + (size_t)bq * sAbat;
    const bf16* Bbh = Bh + (size_t)bq * sBbat;
    const bf16* Bbl = Bl + (size_t)bq * sBbat;

    if (tri) { int need = (am0 >> 6) + 2; if (need < nchunks) nchunks = need; }

    const int wm = (wid >> 2) * 64, wn = (wid & 3) * 32;
    const int aRow = lane & 15, aGrp = lane >> 4;
    const int bRow = (lane & 7) + ((lane >> 4) << 3), bGrp = (lane >> 3) & 1;

    auto issue = [&](int c, int st) {
        uint32_t sb = ub + st * 65536;
#pragma unroll
        for (int i = 0; i < 4; ++i) {
            int idx = i * 256 + tid;
            int row = idx >> 3, seg = idx & 7;
            uint32_t so = sb + (uint32_t)(row * 128 + ((seg ^ (row & 7)) << 4));
            const bf16 *pah, *pal;
            if (c < ksplit) {
                size_t o = (size_t)(am0 + row) * lda1 + c * 64 + seg * 8;
                pah = A1h + o; pal = A1l + o;
            } else {
                size_t o = (size_t)(am0 + row) * lda2 + (c - ksplit) * 64 + seg * 8;
                pah = Ah2 + o; pal = Al2 + o;
            }
            size_t ob = (size_t)(bn * 128 + row) * ldb + c * 64 + seg * 8;
            CP_ASYNC16(so,         pah);
            CP_ASYNC16(so + 16384, pal);
            CP_ASYNC16(so + 32768, Bbh + ob);
            CP_ASYNC16(so + 49152, Bbl + ob);
        }
        CP_COMMIT();
    };

    float acc[4][4][4];
#pragma unroll
    for (int i = 0; i < 4; i++)
#pragma unroll
        for (int j = 0; j < 4; j++)
#pragma unroll
            for (int q = 0; q < 4; q++) acc[i][j][q] = 0.f;

    issue(0, 0);
    for (int c = 0; c < nchunks; ++c) {
        if (c + 1 < nchunks) { issue(c + 1, (c + 1) & 1); CP_WAIT1(); }
        else CP_WAIT0();
        __syncthreads();

        uint32_t uAh = ub + (c & 1) * 65536;
        uint32_t uAl = uAh + 16384, uBh = uAh + 32768, uBl = uAh + 49152;
#pragma unroll
        for (int ks = 0; ks < 4; ++ks) {
            uint32_t bh[8], bl[8];
#pragma unroll
            for (int h = 0; h < 2; ++h) {
                int row = wn + h * 16 + bRow;
                int grp = 2 * ks + bGrp;
                uint32_t off = (uint32_t)(row * 128 + ((grp ^ (row & 7)) << 4));
                LDSM4(bh[h*4+0], bh[h*4+1], bh[h*4+2], bh[h*4+3], uBh + off);
                LDSM4(bl[h*4+0], bl[h*4+1], bl[h*4+2], bl[h*4+3], uBl + off);
            }
#pragma unroll
            for (int mi = 0; mi < 4; ++mi) {
                int row = wm + mi * 16 + aRow;
                int grp = 2 * ks + aGrp;
                uint32_t off = (uint32_t)(row * 128 + ((grp ^ (row & 7)) << 4));
                uint32_t ah[4], al[4];
                LDSM4(ah[0], ah[1], ah[2], ah[3], uAh + off);
                LDSM4(al[0], al[1], al[2], al[3], uAl + off);
#pragma unroll
                for (int ni = 0; ni < 4; ++ni) {
                    int bx = (ni >> 1) * 4 + (ni & 1) * 2;
                    MMA16816(acc[mi][ni], ah[0], ah[1], ah[2], ah[3], bh[bx], bh[bx+1]);
                    MMA16816(acc[mi][ni], ah[0], ah[1], ah[2], ah[3], bl[bx], bl[bx+1]);
                    MMA16816(acc[mi][ni], al[0], al[1], al[2], al[3], bh[bx], bh[bx+1]);
                }
            }
        }
        __syncthreads();
    }

    // epilogue
#pragma unroll
    for (int mi = 0; mi < 4; ++mi) {
#pragma unroll
        for (int ni = 0; ni < 4; ++ni) {
            int row = bm * 128 + wm + mi * 16 + (lane >> 2);
            int col = bn * 128 + wn + ni * 8 + ((lane & 3) << 1);
            float b0 = 0.f, b1 = 0.f;
            if (bias1) { b0 = bias1[col]; b1 = bias1[col + 1]; }
            if (bias2) { b0 += bias2[col]; b1 += bias2[col + 1]; }
            float v00 = acc[mi][ni][0] + b0, v01 = acc[mi][ni][1] + b1;
            float v10 = acc[mi][ni][2] + b0, v11 = acc[mi][ni][3] + b1;
            if (actTanh) {
                v00 = tfast(v00); v01 = tfast(v01);
                v10 = tfast(v10); v11 = tfast(v11);
            }
            size_t i0 = (size_t)row * N + col;
            size_t i1 = (size_t)(row + 8) * N + col;
            if (Cf) {
                *(float2*)&Cf[i0] = make_float2(v00, v01);
                *(float2*)&Cf[i1] = make_float2(v10, v11);
            }
            if (Chi) {
                if (outHalf) {
                    __half* H = (__half*)Chi;
                    __half* L = (__half*)Clo;
                    __half h00 = __float2half(v00), h01 = __float2half(v01);
                    __half h10 = __float2half(v10), h11 = __float2half(v11);
                    __half2 p;
                    p.x = h00; p.y = h01; *(__half2*)&H[i0] = p;
                    p.x = h10; p.y = h11; *(__half2*)&H[i1] = p;
                    p.x = __float2half(v00 - __half2float(h00));
                    p.y = __float2half(v01 - __half2float(h01));
                    *(__half2*)&L[i0] = p;
                    p.x = __float2half(v10 - __half2float(h10));
                    p.y = __float2half(v11 - __half2float(h11));
                    *(__half2*)&L[i1] = p;
                } else {
                    bf16 h00 = __float2bfloat16(v00), h01 = __float2bfloat16(v01);
                    bf16 h10 = __float2bfloat16(v10), h11 = __float2bfloat16(v11);
                    __nv_bfloat162 p;
                    p.x = h00; p.y = h01; *(__nv_bfloat162*)&Chi[i0] = p;
                    p.x = h10; p.y = h11; *(__nv_bfloat162*)&Chi[i1] = p;
                    p.x = __float2bfloat16(v00 - __bfloat162float(h00));
                    p.y = __float2bfloat16(v01 - __bfloat162float(h01));
                    *(__nv_bfloat162*)&Clo[i0] = p;
                    p.x = __float2bfloat16(v10 - __bfloat162float(h10));
                    p.y = __float2bfloat16(v11 - __bfloat162float(h11));
                    *(__nv_bfloat162*)&Clo[i1] = p;
                }
            }
        }
    }
}

// ---------------- K7 decoder: fp16 2-term GEMM (A=2-term, B=hi only) ----------------
#define MMA7_SMEM (2 * 49152)

__global__ __launch_bounds__(256)
void k_mma7(const __half* __restrict__ Ah, const __half* __restrict__ Al,
            const __half* __restrict__ Bh, int N,
            const float* __restrict__ bias, float* __restrict__ Cf)
{
    extern __shared__ char dsm[];
    const uint32_t ub = smem_u32(dsm);
    const int tid = threadIdx.x, lane = tid & 31, wid = tid >> 5;
    const int bm = blockIdx.x, bn = blockIdx.y;
    const int wm = (wid >> 2) * 64, wn = (wid & 3) * 32;
    const int aRow = lane & 15, aGrp = lane >> 4;
    const int bRow = (lane & 7) + ((lane >> 4) << 3), bGrp = (lane >> 3) & 1;

    auto issue = [&](int c, int st) {
        uint32_t sb = ub + st * 49152;
#pragma unroll
        for (int i = 0; i < 4; ++i) {
            int idx = i * 256 + tid;
            int row = idx >> 3, seg = idx & 7;
            uint32_t so = sb + (uint32_t)(row * 128 + ((seg ^ (row & 7)) << 4));
            size_t oa = (size_t)(bm * 128 + row) * 512 + c * 64 + seg * 8;
            size_t ob = (size_t)(bn * 128 + row) * 512 + c * 64 + seg * 8;
            CP_ASYNC16(so,         Ah + oa);
            CP_ASYNC16(so + 16384, Al + oa);
            CP_ASYNC16(so + 32768, Bh + ob);
        }
        CP_COMMIT();
    };

    float acc[4][4][4];
#pragma unroll
    for (int i = 0; i < 4; i++)
#pragma unroll
        for (int j = 0; j < 4; j++)
#pragma unroll
            for (int q = 0; q < 4; q++) acc[i][j][q] = 0.f;

    issue(0, 0);
    for (int c = 0; c < 8; ++c) {
        if (c + 1 < 8) { issue(c + 1, (c + 1) & 1); CP_WAIT1(); }
        else CP_WAIT0();
        __syncthreads();

        uint32_t uA = ub + (c & 1) * 49152;
        uint32_t uAl = uA + 16384, uB = uA + 32768;
#pragma unroll
        for (int ks = 0; ks < 4; ++ks) {
            uint32_t bh[8];
#pragma unroll
            for (int h = 0; h < 2; ++h) {
                int row = wn + h * 16 + bRow;
                int grp = 2 * ks + bGrp;
                uint32_t off = (uint32_t)(row * 128 + ((grp ^ (row & 7)) << 4));
                LDSM4(bh[h*4+0], bh[h*4+1], bh[h*4+2], bh[h*4+3], uB + off);
            }
#pragma unroll
            for (int mi = 0; mi < 4; ++mi) {
                int row = wm + mi * 16 + aRow;
                int grp = 2 * ks + aGrp;
                uint32_t off = (uint32_t)(row * 128 + ((grp ^ (row & 7)) << 4));
                uint32_t ah[4], al[4];
                LDSM4(ah[0], ah[1], ah[2], ah[3], uA + off);
                LDSM4(al[0], al[1], al[2], al[3], uAl + off);
#pragma unroll
                for (int ni = 0; ni < 4; ++ni) {
                    int bx = (ni >> 1) * 4 + (ni & 1) * 2;
                    MMAF16(acc[mi][ni], ah[0], ah[1], ah[2], ah[3], bh[bx], bh[bx+1]);
                    MMAF16(acc[mi][ni], al[0], al[1], al[2], al[3], bh[bx], bh[bx+1]);
                }
            }
        }
        __syncthreads();
    }

#pragma unroll
    for (int mi = 0; mi < 4; ++mi) {
#pragma unroll
        for (int ni = 0; ni < 4; ++ni) {
            int row = bm * 128 + wm + mi * 16 + (lane >> 2);
            int col = bn * 128 + wn + ni * 8 + ((lane & 3) << 1);
            float b0 = bias[col], b1 = bias[col + 1];
            size_t i0 = (size_t)row * N + col;
            size_t i1 = (size_t)(row + 8) * N + col;
            *(float2*)&Cf[i0] = make_float2(acc[mi][ni][0] + b0, acc[mi][ni][1] + b1);
            *(float2*)&Cf[i1] = make_float2(acc[mi][ni][2] + b0, acc[mi][ni][3] + b1);
        }
    }
}

// ---------------- LSTM-1 persistent kernel (R11-proven atomic barrier) ----------------
__global__ __launch_bounds__(256)
void k_lstm1(const float* __restrict__ Whh)
{
    __shared__ float hsm[2048];
    __shared__ float gsum[64];
    __shared__ float csm[16];
    const int tid  = threadIdx.x;
    const int u0   = blockIdx.x * 4;
    const int warp = tid >> 5, lane = tid & 31;
    const int grp  = blockIdx.x >> 4;

    const int r0 = 2 * warp, r1 = 2 * warp + 1;
    const float* W0 = Whh + ((size_t)((r0 >> 2) * 512 + u0 + (r0 & 3))) * 512;
    const float* W1 = Whh + ((size_t)((r1 >> 2) * 512 + u0 + (r1 & 3))) * 512;
    float4 w0[4], w1[4];
#pragma unroll
    for (int q = 0; q < 4; ++q) {
        w0[q] = *(const float4*)(W0 + 4 * lane + 128 * q);
        w1[q] = *(const float4*)(W1 + 4 * lane + 128 * q);
    }
    if (tid < 16) csm[tid] = 0.f;
    __syncthreads();

    for (int t = 0; t < T_; ++t) {
        float xg[4];
        if (tid < 16) {
            int uu = tid >> 2, b = tid & 3;
            const float* xr = g_xw + (size_t)(b * T_ + t) * 2048 + u0 + uu;
            xg[0] = xr[0]; xg[1] = xr[512]; xg[2] = xr[1024]; xg[3] = xr[1536];
        }
        if (t > 0) {
            for (int i = tid; i < 512; i += 256) {
                int b = i >> 7, k4 = i & 127;
                ((float4*)hsm)[i] =
                    ((const float4*)(g_enc + (size_t)(b * T_ + t - 1) * 512))[k4];
            }
        } else {
            for (int i = tid; i < 2048; i += 256) hsm[i] = 0.f;
        }
        __syncthreads();

        float s[8];
#pragma unroll
        for (int b = 0; b < 4; ++b) {
            const float* hb = hsm + b * 512 + 4 * lane;
            float4 h0 = *(const float4*)(hb);
            float4 h1 = *(const float4*)(hb + 128);
            float4 h2 = *(const float4*)(hb + 256);
            float4 h3 = *(const float4*)(hb + 384);
            float a0, a1;
            a0 = w0[0].x*h0.x + w0[0].y*h0.y + w0[0].z*h0.z + w0[0].w*h0.w;
            a0 += w0[1].x*h1.x + w0[1].y*h1.y + w0[1].z*h1.z + w0[1].w*h1.w;
            a0 += w0[2].x*h2.x + w0[2].y*h2.y + w0[2].z*h2.z + w0[2].w*h2.w;
            a0 += w0[3].x*h3.x + w0[3].y*h3.y + w0[3].z*h3.z + w0[3].w*h3.w;
            a1 = w1[0].x*h0.x + w1[0].y*h0.y + w1[0].z*h0.z + w1[0].w*h0.w;
            a1 += w1[1].x*h1.x + w1[1].y*h1.y + w1[1].z*h1.z + w1[1].w*h1.w;
            a1 += w1[2].x*h2.x + w1[2].y*h2.y + w1[2].z*h2.z + w1[2].w*h2.w;
            a1 += w1[3].x*h3.x + w1[3].y*h3.y + w1[3].z*h3.z + w1[3].w*h3.w;
            s[b * 2] = a0; s[b * 2 + 1] = a1;
        }
#pragma unroll
        for (int i = 0; i < 8; ++i) {
            s[i] += __shfl_xor_sync(0xffffffffu, s[i], 16);
            s[i] += __shfl_xor_sync(0xffffffffu, s[i], 8);
            s[i] += __shfl_xor_sync(0xffffffffu, s[i], 4);
            s[i] += __shfl_xor_sync(0xffffffffu, s[i], 2);
            s[i] += __shfl_xor_sync(0xffffffffu, s[i], 1);
        }
        if (lane < 8) {
            float v = (lane < 4) ? s[2 * lane] : s[2 * (lane - 4) + 1];
            gsum[warp * 8 + lane] = v;
        }
        __syncthreads();

        if (tid < 16) {
            int uu = tid >> 2, bb = tid & 3;
            float gi = gsum[((0 * 4 + uu) << 2) | bb] + xg[0];
            float gf = gsum[((1 * 4 + uu) << 2) | bb] + xg[1];
            float gg = gsum[((2 * 4 + uu) << 2) | bb] + xg[2];
            float go = gsum[((3 * 4 + uu) << 2) | bb] + xg[3];
            float c = sigf(gf) * csm[tid] + sigf(gi) * tfast(gg);
            csm[tid] = c;
            float h = sigf(go) * tfast(c);
            int u  = u0 + uu;
            size_t bt = (size_t)(bb * T_ + t);
            g_enc[bt * 512 + u] = h;
            bf16 hh = __float2bfloat16(h);
            bf16 hl = __float2bfloat16(h - __bfloat162float(hh));
            g_enc_hi[bt * 512 + u] = hh;
            g_enc_lo[bt * 512 + u] = hl;
            size_t ei = ((size_t)bb * 512 + u) * 1024 + t;
            g_et_hi[ei] = hh;
            g_et_lo[ei] = hl;
            __threadfence();
        }
        __syncthreads();

        if (tid == 0) {
            unsigned a = atomicAdd(&g_cnt[grp * 32], 1u);
            if (a == (unsigned)((t + 1) * 16 - 1)) atomicAdd(&g_root, 1u);
            while (*(volatile unsigned*)&g_root < 8u * (unsigned)(t + 1)) { }
        }
        __syncthreads();
    }
}

// ---------------- LSTM-2: 4 independent warps ----------------
__global__ __launch_bounds__(128)
void k_lstm2(const float* __restrict__ Wp_hh,
             const float* __restrict__ Wmu, const float* __restrict__ bmu,
             const float* __restrict__ Wsig, const float* __restrict__ bsig,
             const int* __restrict__ pad)
{
    __shared__ float wp[1600];
    __shared__ float wmu_s[60];
    __shared__ float wsig_s[20];
    __shared__ float bconst[4];
    __shared__ float hp[4][20];
    __shared__ float gp[4][80];
    __shared__ float tmp[4][4];
    const int tid = threadIdx.x;
    const int b = tid >> 5, lane = tid & 31;

    for (int i = tid; i < 1600; i += 128) wp[i] = Wp_hh[i];
    for (int i = tid; i < 60; i += 128) wmu_s[i] = Wmu[i];
    if (tid < 20) wsig_s[tid] = Wsig[tid];
    if (tid < 3) bconst[tid] = bmu[tid];
    if (tid == 3) bconst[3] = bsig[0];
    if (tid < 80) hp[tid / 20][tid % 20] = 0.f;
    __syncthreads();

    const float invL = 1.f / (float)pad[b];
    float cc = 0.f;
    float mu_prev = 0.f;
    const int r0 = lane, r1 = lane + 32, r2 = lane + 64;
    const int r2c = (r2 < 80) ? r2 : 79;

    float px0 = g_pxw[(size_t)(b * T_) * 128 + r0];
    float px1 = g_pxw[(size_t)(b * T_) * 128 + r1];
    float px2 = (r2 < 80) ? g_pxw[(size_t)(b * T_) * 128 + r2] : 0.f;

    for (int t = 0; t < T_; ++t) {
        float s0 = px0, s1 = px1, s2 = px2;
#pragma unroll
        for (int k = 0; k < 20; ++k) {
            float h = hp[b][k];
            s0 = fmaf(wp[r0 * 20 + k], h, s0);
            s1 = fmaf(wp[r1 * 20 + k], h, s1);
            s2 = fmaf(wp[r2c * 20 + k], h, s2);
        }
        gp[b][r0] = s0;
        gp[b][r1] = s1;
        if (r2 < 80) gp[b][r2] = s2;
        if (t + 1 < T_) {
            size_t base = (size_t)(b * T_ + t + 1) * 128;
            px0 = g_pxw[base + r0];
            px1 = g_pxw[base + r1];
            if (r2 < 80) px2 = g_pxw[base + r2];
        }
        __syncwarp();
        if (lane < 20) {
            float gi = gp[b][lane], gf = gp[b][20 + lane];
            float gg = gp[b][40 + lane], go = gp[b][60 + lane];
            cc = sigf(gf) * cc + sigf(gi) * tfast(gg);
            hp[b][lane] = sigf(go) * tfast(cc);
        }
        __syncwarp();
        if (lane >= 20 && lane < 24) {
            int s = lane - 20;
            const float* wv = (s < 3) ? &wmu_s[s * 20] : wsig_s;
            float acc = bconst[s];
#pragma unroll
            for (int k = 0; k < 20; ++k) acc = fmaf(wv[k], hp[b][k], acc);
            tmp[b][s] = acc;
        }
        __syncwarp();
        if (lane == 0) {
            float m0 = fmaxf(tmp[b][0], 0.f);
            float m1 = fmaxf(tmp[b][1], 0.f);
            float m2 = fmaxf(tmp[b][2], 0.f);
            float sg = sigf(tmp[b][3]);
            float mu = fmaf(m0, mu_prev, (m1 + m2 * (float)(t + 1)) * invL);
            mu_prev = mu;
            g_mu[b * T_ + t]  = mu;
            g_sig[b * T_ + t] = sg;
        }
    }
}

// ---------------- attention weights: compute, normalize, split to bf16 ----------
__global__ __launch_bounds__(256)
void k_wnorm()
{
    __shared__ float wsm[1024];
    __shared__ float red[8];
    const int tid = threadIdx.x, lane = tid & 31, warp = tid >> 5;
    const int bj = blockIdx.x;
    const int b = bj >> 10, j = bj & 1023;
    const float mu = g_mu[bj];
    const float sg = g_sig[bj];
    const float invd  = 1.f / (2.f * sg * sg + 0.001f);
    const float invj1 = 1.f / (float)(j + 1);

    float lsum = 0.f;
#pragma unroll
    for (int i = 0; i < 4; ++i) {
        int t = tid + i * 256;
        float w = 0.f;
        if (t <= j) {
            float r = (float)t * invj1 - mu;
            w = __expf(-r * r * invd);
        }
        wsm[t] = w;
        lsum += w;
    }
    lsum += __shfl_xor_sync(0xffffffffu, lsum, 16);
    lsum += __shfl_xor_sync(0xffffffffu, lsum, 8);
    lsum += __shfl_xor_sync(0xffffffffu, lsum, 4);
    lsum += __shfl_xor_sync(0xffffffffu, lsum, 2);
    lsum += __shfl_xor_sync(0xffffffffu, lsum, 1);
    if (lane == 0) red[warp] = lsum;
    __syncthreads();
    float tot = red[0] + red[1] + red[2] + red[3] + red[4] + red[5] + red[6] + red[7];
    const float scale = 1.f / fmaxf(tot, 1e-12f);

    size_t base = ((size_t)b << 20) + ((size_t)j << 10);
#pragma unroll
    for (int i = 0; i < 4; ++i) {
        int t = tid + i * 256;
        float v = wsm[t] * scale;
        bf16 h = __float2bfloat16(v);
        g_w_hi[base + t] = h;
        g_w_lo[base + t] = __float2bfloat16(v - __bfloat162float(h));
    }
}

// ---------------- launch ----------------
extern "C" void kernel_launch(void* const* d_in, const int* in_sizes, int n_in,
                              void* d_out, int out_size)
{
    const int*   ids      = (const int*)d_in[0];
    const int*   pad      = (const int*)d_in[1];
    const float* emb      = (const float*)d_in[2];
    const float* dec_bias = (const float*)d_in[3];
    const float* Wih      = (const float*)d_in[4];
    const float* Whh      = (const float*)d_in[5];
    const float* bih      = (const float*)d_in[6];
    const float* bhh      = (const float*)d_in[7];
    const float* Wp_ih    = (const float*)d_in[8];
    const float* Wp_hh    = (const float*)d_in[9];
    const float* bp_ih    = (const float*)d_in[10];
    const float* bp_hh    = (const float*)d_in[11];
    const float* Wmu      = (const float*)d_in[12];
    const float* bmu      = (const float*)d_in[13];
    const float* Wsig     = (const float*)d_in[14];
    const float* bsig     = (const float*)d_in[15];
    const float* Wc       = (const float*)d_in[16];
    const float* bc       = (const float*)d_in[17];
    float* out = (float*)d_out;

    float *p_xw, *p_pxw, *p_bp;
    bf16 *p_ehi, *p_elo, *p_whi, *p_wlo, *p_xhi, *p_xlo;
    bf16 *p_nhi, *p_nlo, *p_ethi, *p_etlo, *p_awhi, *p_awlo;
    bf16 *p_cxhi, *p_cxlo, *p_wchi, *p_wclo, *p_wphi, *p_wplo;
    __half *p_ef, *p_cfh, *p_cfl;
    cudaGetSymbolAddress((void**)&p_xw,    g_xw);
    cudaGetSymbolAddress((void**)&p_pxw,   g_pxw);
    cudaGetSymbolAddress((void**)&p_bp,    g_bp);
    cudaGetSymbolAddress((void**)&p_ehi,   g_emb_hi);
    cudaGetSymbolAddress((void**)&p_elo,   g_emb_lo);
    cudaGetSymbolAddress((void**)&p_ef,    g_emb_f);
    cudaGetSymbolAddress((void**)&p_whi,   g_wih_hi);
    cudaGetSymbolAddress((void**)&p_wlo,   g_wih_lo);
    cudaGetSymbolAddress((void**)&p_xhi,   g_x_hi);
    cudaGetSymbolAddress((void**)&p_xlo,   g_x_lo);
    cudaGetSymbolAddress((void**)&p_nhi,   g_enc_hi);
    cudaGetSymbolAddress((void**)&p_nlo,   g_enc_lo);
    cudaGetSymbolAddress((void**)&p_ethi,  g_et_hi);
    cudaGetSymbolAddress((void**)&p_etlo,  g_et_lo);
    cudaGetSymbolAddress((void**)&p_awhi,  g_w_hi);
    cudaGetSymbolAddress((void**)&p_awlo,  g_w_lo);
    cudaGetSymbolAddress((void**)&p_cxhi,  g_ctx_hi);
    cudaGetSymbolAddress((void**)&p_cxlo,  g_ctx_lo);
    cudaGetSymbolAddress((void**)&p_cfh,   g_comb_fh);
    cudaGetSymbolAddress((void**)&p_cfl,   g_comb_fl);
    cudaGetSymbolAddress((void**)&p_wchi,  g_wc_hi);
    cudaGetSymbolAddress((void**)&p_wclo,  g_wc_lo);
    cudaGetSymbolAddress((void**)&p_wphi,  g_wp_hi);
    cudaGetSymbolAddress((void**)&p_wplo,  g_wp_lo);

    cudaFuncSetAttribute(k_mma, cudaFuncAttributeMaxDynamicSharedMemorySize, MMA_SMEM);
    cudaFuncSetAttribute(k_mma7, cudaFuncAttributeMaxDynamicSharedMemorySize, MMA7_SMEM);

    const int NOB = 1 << 28;

    k_split<<<(V_ * H_ + 255) / 256, 256>>>(emb, p_ehi, p_elo, p_ef, V_ * H_);
    k_split<<<(4 * H_ * H_ + 255) / 256, 256>>>(Wih, p_whi, p_wlo, nullptr, 4 * H_ * H_);
    k_split<<<(H_ * 2 * H_ + 255) / 256, 256>>>(Wc, p_wchi, p_wclo, nullptr, H_ * 2 * H_);
    k_split<<<(80 * H_ + 255) / 256, 256>>>(Wp_ih, p_wphi, p_wplo, nullptr, 80 * H_);
    k_padbias<<<1, 128>>>(bp_ih, bp_hh);
    k_embed_bf<<<(BT * H_ + 255) / 256, 256>>>(ids);

    // K1: xw = x @ Wih^T + bih + bhh -> fp32 [4096, 2048]
    k_mma<<<dim3(16, 32), 256, MMA_SMEM>>>(
        p_xhi, p_xlo, 512, nullptr, nullptr, 0, 8, 8, NOB, 0,
        p_whi, p_wlo, 512, 0, 2048, bih, bhh, p_xw, nullptr, nullptr, 0, 0, 0);

    // K2: LSTM-1 recurrence
    k_lstm1<<<NB1, 256>>>(Whh);

    // K3: pxw = enc @ Wp_ih^T + biases -> fp32 [4096, 128pad]
    k_mma<<<dim3(1, 32), 256, MMA_SMEM>>>(
        p_nhi, p_nlo, 512, nullptr, nullptr, 0, 8, 8, NOB, 0,
        p_wphi, p_wplo, 512, 0, 128, p_bp, nullptr, p_pxw, nullptr, nullptr, 0, 0, 0);

    // K4: LSTM-2 + mu/sigma scan
    k_lstm2<<<1, 128>>>(Wp_hh, Wmu, bmu, Wsig, bsig, pad);

    // K5a: attention weights
    k_wnorm<<<BT, 256>>>();

    // K5b: ctx = w @ enc (batched, triangular skip) -> bf16 hi/lo
    k_mma<<<dim3(4, 32), 256, MMA_SMEM>>>(
        p_awhi, p_awlo, 1024, nullptr, nullptr, 0, 16, 16, 8, (size_t)T_ * T_,
        p_ethi, p_etlo, 1024, (size_t)H_ * T_, 512,
        nullptr, nullptr, nullptr, p_cxhi, p_cxlo, 0, 1, 0);

    // K6: combined = tanh([ctx, enc] @ Wc^T + bc) -> fp16 hi/lo (for K7)
    k_mma<<<dim3(4, 32), 256, MMA_SMEM>>>(
        p_cxhi, p_cxlo, 512, p_nhi, p_nlo, 512, 8, 16, NOB, 0,
        p_wchi, p_wclo, 1024, 0, 512, bc, nullptr,
        nullptr, (bf16*)p_cfh, (bf16*)p_cfl, 1, 0, 1);

    // K7: logits = combined @ emb^T + dec_bias -> fp32 (fp16 2-term)
    k_mma7<<<dim3(32, 250), 256, MMA7_SMEM>>>(
        p_cfh, p_cfl, p_ef, V_, dec_bias, out);
}

// round 15
// speedup vs baseline: 2.5144x; 1.0756x over previous
#include <cuda_runtime.h>
#include <cuda_bf16.h>
#include <cuda_fp16.h>
#include <cstdint>
#include <math.h>

#define B_ 4
#define T_ 1024
#define H_ 512
#define P_ 20
#define V_ 32000
#define BT (B_*T_)
#define NB1 128

typedef __nv_bfloat16 bf16;

// ---------------- scratch (device globals) ----------------
__device__ __align__(256) float g_xw[BT*2048];
__device__ __align__(256) float g_enc[BT*512];
__device__ __align__(256) float g_pxw[BT*128];
__device__ float g_mu[BT];
__device__ float g_sig[BT];
__device__ unsigned g_cnt[256];
__device__ unsigned g_root;
__device__ float g_bp[128];

__device__ __align__(256) bf16 g_emb_hi[V_*H_];
__device__ __align__(256) bf16 g_emb_lo[V_*H_];
__device__ __align__(256) __half g_emb_f[V_*H_];
__device__ __align__(256) bf16 g_wih_hi[4*H_*H_];
__device__ __align__(256) bf16 g_wih_lo[4*H_*H_];
__device__ __align__(256) bf16 g_x_hi[BT*H_];
__device__ __align__(256) bf16 g_x_lo[BT*H_];
__device__ __align__(256) bf16 g_enc_hi[BT*H_];
__device__ __align__(256) bf16 g_enc_lo[BT*H_];
__device__ __align__(256) bf16 g_et_hi[B_*H_*T_];
__device__ __align__(256) bf16 g_et_lo[B_*H_*T_];
__device__ __align__(256) bf16 g_w_hi[B_*T_*T_];
__device__ __align__(256) bf16 g_w_lo[B_*T_*T_];
__device__ __align__(256) bf16 g_ctx_hi[BT*H_];
__device__ __align__(256) bf16 g_ctx_lo[BT*H_];
__device__ __align__(256) __half g_comb_fh[BT*H_];
__device__ __align__(256) bf16 g_wc_hi[H_*2*H_];
__device__ __align__(256) bf16 g_wc_lo[H_*2*H_];
__device__ __align__(256) bf16 g_wp_hi[128*H_];
__device__ __align__(256) bf16 g_wp_lo[128*H_];

__device__ __forceinline__ float sigf(float x) { return 1.f / (1.f + __expf(-x)); }
__device__ __forceinline__ float tfast(float x) {
    float a = fabsf(x);
    float e = __expf(2.f * a);
    float t = 1.f - 2.f / (1.f + e);
    return copysignf(t, x);
}

__device__ __forceinline__ uint32_t smem_u32(const void* p) {
    uint32_t a;
    asm("{ .reg .u64 t; cvta.to.shared.u64 t, %1; cvt.u32.u64 %0, t; }"
        : "=r"(a) : "l"(p));
    return a;
}

#define CP_ASYNC16(s, g) \
    asm volatile("cp.async.cg.shared.global [%0], [%1], 16;" :: "r"(s), "l"(g))
#define CP_COMMIT() asm volatile("cp.async.commit_group;" ::: "memory")
#define CP_WAIT1()  asm volatile("cp.async.wait_group 1;" ::: "memory")
#define CP_WAIT0()  asm volatile("cp.async.wait_group 0;" ::: "memory")

#define LDSM4(r0, r1, r2, r3, a)                                             \
    asm volatile("ldmatrix.sync.aligned.m8n8.x4.shared.b16 {%0,%1,%2,%3}, [%4];" \
        : "=r"(r0), "=r"(r1), "=r"(r2), "=r"(r3) : "r"(a))

#define MMA16816(c, A0, A1, A2, A3, B0, B1)                                  \
    asm volatile("mma.sync.aligned.m16n8k16.row.col.f32.bf16.bf16.f32 "      \
        "{%0,%1,%2,%3}, {%4,%5,%6,%7}, {%8,%9}, {%0,%1,%2,%3};"              \
        : "+f"((c)[0]), "+f"((c)[1]), "+f"((c)[2]), "+f"((c)[3])             \
        : "r"(A0), "r"(A1), "r"(A2), "r"(A3), "r"(B0), "r"(B1))

#define MMAF16(c, A0, A1, A2, A3, B0, B1)                                    \
    asm volatile("mma.sync.aligned.m16n8k16.row.col.f32.f16.f16.f32 "        \
        "{%0,%1,%2,%3}, {%4,%5,%6,%7}, {%8,%9}, {%0,%1,%2,%3};"              \
        : "+f"((c)[0]), "+f"((c)[1]), "+f"((c)[2]), "+f"((c)[3])             \
        : "r"(A0), "r"(A1), "r"(A2), "r"(A3), "r"(B0), "r"(B1))

// ---------------- split fp32 -> bf16 hi/lo (+ optional fp16) ----------------
__global__ void k_split(const float* __restrict__ src,
                        bf16* __restrict__ hi, bf16* __restrict__ lo,
                        __half* __restrict__ fh, int n)
{
    int i = blockIdx.x * blockDim.x + threadIdx.x;
    if (i < n) {
        float v = src[i];
        bf16 h = __float2bfloat16(v);
        hi[i] = h;
        lo[i] = __float2bfloat16(v - __bfloat162float(h));
        if (fh) fh[i] = __float2half(v);
    }
}

__global__ void k_padbias(const float* __restrict__ b1, const float* __restrict__ b2)
{
    int i = threadIdx.x;
    if (i < 80) g_bp[i] = b1[i] + b2[i];
}

// ---------------- embedding gather + barrier counter reset ----------------
__global__ void k_embed_bf(const int* __restrict__ ids)
{
    if (blockIdx.x == 0) {
        if (threadIdx.x == 0) g_root = 0;
        if (threadIdx.x < 8) g_cnt[threadIdx.x * 32] = 0;
    }
    int i = blockIdx.x * blockDim.x + threadIdx.x;
    if (i < BT * H_) {
        int bt = i >> 9;
        int h  = i & 511;
        size_t src = (size_t)ids[bt] * H_ + h;
        g_x_hi[i] = g_emb_hi[src];
        g_x_lo[i] = g_emb_lo[src];
    }
}

// ---------------- generalized bf16x3 HMMA GEMM, 2-stage cp.async (proven) --------
#define MMA_SMEM (2 * 65536)

__global__ __launch_bounds__(256)
void k_mma(const bf16* __restrict__ Ah1, const bf16* __restrict__ Al1, int lda1,
           const bf16* __restrict__ Ah2, const bf16* __restrict__ Al2, int lda2,
           int ksplit, int nchunks, int mbpb, size_t sAbat,
           const bf16* __restrict__ Bh, const bf16* __restrict__ Bl, int ldb, size_t sBbat,
           int N, const float* __restrict__ bias1, const float* __restrict__ bias2,
           float* __restrict__ Cf, bf16* __restrict__ Chi, bf16* __restrict__ Clo,
           int actTanh, int tri, int outHalf)
{
    extern __shared__ char dsm[];
    const uint32_t ub = smem_u32(dsm);
    const int tid = threadIdx.x, lane = tid & 31, wid = tid >> 5;
    const int bm = blockIdx.y, bn = blockIdx.x;
    const int bq = bm / mbpb;
    const int am0 = (bm - bq * mbpb) * 128;
    const bf16* A1h = Ah1 + (size_t)bq * sAbat;
    const bf16* A1l = Al1 + (size_t)bq * sAbat;
    const bf16* Bbh = Bh + (size_t)bq * sBbat;
    const bf16* Bbl = Bl + (size_t)bq * sBbat;

    if (tri) { int need = (am0 >> 6) + 2; if (need < nchunks) nchunks = need; }

    const int wm = (wid >> 2) * 64, wn = (wid & 3) * 32;
    const int aRow = lane & 15, aGrp = lane >> 4;
    const int bRow = (lane & 7) + ((lane >> 4) << 3), bGrp = (lane >> 3) & 1;

    auto issue = [&](int c, int st) {
        uint32_t sb = ub + st * 65536;
#pragma unroll
        for (int i = 0; i < 4; ++i) {
            int idx = i * 256 + tid;
            int row = idx >> 3, seg = idx & 7;
            uint32_t so = sb + (uint32_t)(row * 128 + ((seg ^ (row & 7)) << 4));
            const bf16 *pah, *pal;
            if (c < ksplit) {
                size_t o = (size_t)(am0 + row) * lda1 + c * 64 + seg * 8;
                pah = A1h + o; pal = A1l + o;
            } else {
                size_t o = (size_t)(am0 + row) * lda2 + (c - ksplit) * 64 + seg * 8;
                pah = Ah2 + o; pal = Al2 + o;
            }
            size_t ob = (size_t)(bn * 128 + row) * ldb + c * 64 + seg * 8;
            CP_ASYNC16(so,         pah);
            CP_ASYNC16(so + 16384, pal);
            CP_ASYNC16(so + 32768, Bbh + ob);
            CP_ASYNC16(so + 49152, Bbl + ob);
        }
        CP_COMMIT();
    };

    float acc[4][4][4];
#pragma unroll
    for (int i = 0; i < 4; i++)
#pragma unroll
        for (int j = 0; j < 4; j++)
#pragma unroll
            for (int q = 0; q < 4; q++) acc[i][j][q] = 0.f;

    issue(0, 0);
    for (int c = 0; c < nchunks; ++c) {
        if (c + 1 < nchunks) { issue(c + 1, (c + 1) & 1); CP_WAIT1(); }
        else CP_WAIT0();
        __syncthreads();

        uint32_t uAh = ub + (c & 1) * 65536;
        uint32_t uAl = uAh + 16384, uBh = uAh + 32768, uBl = uAh + 49152;
#pragma unroll
        for (int ks = 0; ks < 4; ++ks) {
            uint32_t bh[8], bl[8];
#pragma unroll
            for (int h = 0; h < 2; ++h) {
                int row = wn + h * 16 + bRow;
                int grp = 2 * ks + bGrp;
                uint32_t off = (uint32_t)(row * 128 + ((grp ^ (row & 7)) << 4));
                LDSM4(bh[h*4+0], bh[h*4+1], bh[h*4+2], bh[h*4+3], uBh + off);
                LDSM4(bl[h*4+0], bl[h*4+1], bl[h*4+2], bl[h*4+3], uBl + off);
            }
#pragma unroll
            for (int mi = 0; mi < 4; ++mi) {
                int row = wm + mi * 16 + aRow;
                int grp = 2 * ks + aGrp;
                uint32_t off = (uint32_t)(row * 128 + ((grp ^ (row & 7)) << 4));
                uint32_t ah[4], al[4];
                LDSM4(ah[0], ah[1], ah[2], ah[3], uAh + off);
                LDSM4(al[0], al[1], al[2], al[3], uAl + off);
#pragma unroll
                for (int ni = 0; ni < 4; ++ni) {
                    int bx = (ni >> 1) * 4 + (ni & 1) * 2;
                    MMA16816(acc[mi][ni], ah[0], ah[1], ah[2], ah[3], bh[bx], bh[bx+1]);
                    MMA16816(acc[mi][ni], ah[0], ah[1], ah[2], ah[3], bl[bx], bl[bx+1]);
                    MMA16816(acc[mi][ni], al[0], al[1], al[2], al[3], bh[bx], bh[bx+1]);
                }
            }
        }
        __syncthreads();
    }

    // epilogue
#pragma unroll
    for (int mi = 0; mi < 4; ++mi) {
#pragma unroll
        for (int ni = 0; ni < 4; ++ni) {
            int row = bm * 128 + wm + mi * 16 + (lane >> 2);
            int col = bn * 128 + wn + ni * 8 + ((lane & 3) << 1);
            float b0 = 0.f, b1 = 0.f;
            if (bias1) { b0 = bias1[col]; b1 = bias1[col + 1]; }
            if (bias2) { b0 += bias2[col]; b1 += bias2[col + 1]; }
            float v00 = acc[mi][ni][0] + b0, v01 = acc[mi][ni][1] + b1;
            float v10 = acc[mi][ni][2] + b0, v11 = acc[mi][ni][3] + b1;
            if (actTanh) {
                v00 = tfast(v00); v01 = tfast(v01);
                v10 = tfast(v10); v11 = tfast(v11);
            }
            size_t i0 = (size_t)row * N + col;
            size_t i1 = (size_t)(row + 8) * N + col;
            if (Cf) {
                *(float2*)&Cf[i0] = make_float2(v00, v01);
                *(float2*)&Cf[i1] = make_float2(v10, v11);
            }
            if (Chi) {
                if (outHalf) {
                    __half* H = (__half*)Chi;
                    __half2 p;
                    p.x = __float2half(v00); p.y = __float2half(v01);
                    *(__half2*)&H[i0] = p;
                    p.x = __float2half(v10); p.y = __float2half(v11);
                    *(__half2*)&H[i1] = p;
                    if (Clo) {
                        __half* L = (__half*)Clo;
                        __half h00 = __float2half(v00), h01 = __float2half(v01);
                        __half h10 = __float2half(v10), h11 = __float2half(v11);
                        p.x = __float2half(v00 - __half2float(h00));
                        p.y = __float2half(v01 - __half2float(h01));
                        *(__half2*)&L[i0] = p;
                        p.x = __float2half(v10 - __half2float(h10));
                        p.y = __float2half(v11 - __half2float(h11));
                        *(__half2*)&L[i1] = p;
                    }
                } else {
                    bf16 h00 = __float2bfloat16(v00), h01 = __float2bfloat16(v01);
                    bf16 h10 = __float2bfloat16(v10), h11 = __float2bfloat16(v11);
                    __nv_bfloat162 p;
                    p.x = h00; p.y = h01; *(__nv_bfloat162*)&Chi[i0] = p;
                    p.x = h10; p.y = h11; *(__nv_bfloat162*)&Chi[i1] = p;
                    if (Clo) {
                        p.x = __float2bfloat16(v00 - __bfloat162float(h00));
                        p.y = __float2bfloat16(v01 - __bfloat162float(h01));
                        *(__nv_bfloat162*)&Clo[i0] = p;
                        p.x = __float2bfloat16(v10 - __bfloat162float(h10));
                        p.y = __float2bfloat16(v11 - __bfloat162float(h11));
                        *(__nv_bfloat162*)&Clo[i1] = p;
                    }
                }
            }
        }
    }
}

// ---------------- K7 decoder: fp16 SINGLE-term GEMM (A=hi, B=hi) ----------------
#define MMA7_SMEM (2 * 32768)

__global__ __launch_bounds__(256)
void k_mma7(const __half* __restrict__ Ah, const __half* __restrict__ Bh, int N,
            const float* __restrict__ bias, float* __restrict__ Cf)
{
    extern __shared__ char dsm[];
    const uint32_t ub = smem_u32(dsm);
    const int tid = threadIdx.x, lane = tid & 31, wid = tid >> 5;
    const int bm = blockIdx.x, bn = blockIdx.y;
    const int wm = (wid >> 2) * 64, wn = (wid & 3) * 32;
    const int aRow = lane & 15, aGrp = lane >> 4;
    const int bRow = (lane & 7) + ((lane >> 4) << 3), bGrp = (lane >> 3) & 1;

    auto issue = [&](int c, int st) {
        uint32_t sb = ub + st * 32768;
#pragma unroll
        for (int i = 0; i < 4; ++i) {
            int idx = i * 256 + tid;
            int row = idx >> 3, seg = idx & 7;
            uint32_t so = sb + (uint32_t)(row * 128 + ((seg ^ (row & 7)) << 4));
            size_t oa = (size_t)(bm * 128 + row) * 512 + c * 64 + seg * 8;
            size_t ob = (size_t)(bn * 128 + row) * 512 + c * 64 + seg * 8;
            CP_ASYNC16(so,         Ah + oa);
            CP_ASYNC16(so + 16384, Bh + ob);
        }
        CP_COMMIT();
    };

    float acc[4][4][4];
#pragma unroll
    for (int i = 0; i < 4; i++)
#pragma unroll
        for (int j = 0; j < 4; j++)
#pragma unroll
            for (int q = 0; q < 4; q++) acc[i][j][q] = 0.f;

    issue(0, 0);
    for (int c = 0; c < 8; ++c) {
        if (c + 1 < 8) { issue(c + 1, (c + 1) & 1); CP_WAIT1(); }
        else CP_WAIT0();
        __syncthreads();

        uint32_t uA = ub + (c & 1) * 32768;
        uint32_t uB = uA + 16384;
#pragma unroll
        for (int ks = 0; ks < 4; ++ks) {
            uint32_t bh[8];
#pragma unroll
            for (int h = 0; h < 2; ++h) {
                int row = wn + h * 16 + bRow;
                int grp = 2 * ks + bGrp;
                uint32_t off = (uint32_t)(row * 128 + ((grp ^ (row & 7)) << 4));
                LDSM4(bh[h*4+0], bh[h*4+1], bh[h*4+2], bh[h*4+3], uB + off);
            }
#pragma unroll
            for (int mi = 0; mi < 4; ++mi) {
                int row = wm + mi * 16 + aRow;
                int grp = 2 * ks + aGrp;
                uint32_t off = (uint32_t)(row * 128 + ((grp ^ (row & 7)) << 4));
                uint32_t ah[4];
                LDSM4(ah[0], ah[1], ah[2], ah[3], uA + off);
#pragma unroll
                for (int ni = 0; ni < 4; ++ni) {
                    int bx = (ni >> 1) * 4 + (ni & 1) * 2;
                    MMAF16(acc[mi][ni], ah[0], ah[1], ah[2], ah[3], bh[bx], bh[bx+1]);
                }
            }
        }
        __syncthreads();
    }

#pragma unroll
    for (int mi = 0; mi < 4; ++mi) {
#pragma unroll
        for (int ni = 0; ni < 4; ++ni) {
            int row = bm * 128 + wm + mi * 16 + (lane >> 2);
            int col = bn * 128 + wn + ni * 8 + ((lane & 3) << 1);
            float b0 = bias[col], b1 = bias[col + 1];
            size_t i0 = (size_t)row * N + col;
            size_t i1 = (size_t)(row + 8) * N + col;
            *(float2*)&Cf[i0] = make_float2(acc[mi][ni][0] + b0, acc[mi][ni][1] + b1);
            *(float2*)&Cf[i1] = make_float2(acc[mi][ni][2] + b0, acc[mi][ni][3] + b1);
        }
    }
}

// ---------------- LSTM-1 persistent kernel (R11-proven atomic barrier) ----------------
__global__ __launch_bounds__(256)
void k_lstm1(const float* __restrict__ Whh)
{
    __shared__ float hsm[2048];
    __shared__ float gsum[64];
    __shared__ float csm[16];
    const int tid  = threadIdx.x;
    const int u0   = blockIdx.x * 4;
    const int warp = tid >> 5, lane = tid & 31;
    const int grp  = blockIdx.x >> 4;

    const int r0 = 2 * warp, r1 = 2 * warp + 1;
    const float* W0 = Whh + ((size_t)((r0 >> 2) * 512 + u0 + (r0 & 3))) * 512;
    const float* W1 = Whh + ((size_t)((r1 >> 2) * 512 + u0 + (r1 & 3))) * 512;
    float4 w0[4], w1[4];
#pragma unroll
    for (int q = 0; q < 4; ++q) {
        w0[q] = *(const float4*)(W0 + 4 * lane + 128 * q);
        w1[q] = *(const float4*)(W1 + 4 * lane + 128 * q);
    }
    if (tid < 16) csm[tid] = 0.f;
    __syncthreads();

    for (int t = 0; t < T_; ++t) {
        float xg[4];
        if (tid < 16) {
            int uu = tid >> 2, b = tid & 3;
            const float* xr = g_xw + (size_t)(b * T_ + t) * 2048 + u0 + uu;
            xg[0] = xr[0]; xg[1] = xr[512]; xg[2] = xr[1024]; xg[3] = xr[1536];
        }
        if (t > 0) {
            for (int i = tid; i < 512; i += 256) {
                int b = i >> 7, k4 = i & 127;
                ((float4*)hsm)[i] =
                    ((const float4*)(g_enc + (size_t)(b * T_ + t - 1) * 512))[k4];
            }
        } else {
            for (int i = tid; i < 2048; i += 256) hsm[i] = 0.f;
        }
        __syncthreads();

        float s[8];
#pragma unroll
        for (int b = 0; b < 4; ++b) {
            const float* hb = hsm + b * 512 + 4 * lane;
            float4 h0 = *(const float4*)(hb);
            float4 h1 = *(const float4*)(hb + 128);
            float4 h2 = *(const float4*)(hb + 256);
            float4 h3 = *(const float4*)(hb + 384);
            float a0, a1;
            a0 = w0[0].x*h0.x + w0[0].y*h0.y + w0[0].z*h0.z + w0[0].w*h0.w;
            a0 += w0[1].x*h1.x + w0[1].y*h1.y + w0[1].z*h1.z + w0[1].w*h1.w;
            a0 += w0[2].x*h2.x + w0[2].y*h2.y + w0[2].z*h2.z + w0[2].w*h2.w;
            a0 += w0[3].x*h3.x + w0[3].y*h3.y + w0[3].z*h3.z + w0[3].w*h3.w;
            a1 = w1[0].x*h0.x + w1[0].y*h0.y + w1[0].z*h0.z + w1[0].w*h0.w;
            a1 += w1[1].x*h1.x + w1[1].y*h1.y + w1[1].z*h1.z + w1[1].w*h1.w;
            a1 += w1[2].x*h2.x + w1[2].y*h2.y + w1[2].z*h2.z + w1[2].w*h2.w;
            a1 += w1[3].x*h3.x + w1[3].y*h3.y + w1[3].z*h3.z + w1[3].w*h3.w;
            s[b * 2] = a0; s[b * 2 + 1] = a1;
        }
#pragma unroll
        for (int i = 0; i < 8; ++i) {
            s[i] += __shfl_xor_sync(0xffffffffu, s[i], 16);
            s[i] += __shfl_xor_sync(0xffffffffu, s[i], 8);
            s[i] += __shfl_xor_sync(0xffffffffu, s[i], 4);
            s[i] += __shfl_xor_sync(0xffffffffu, s[i], 2);
            s[i] += __shfl_xor_sync(0xffffffffu, s[i], 1);
        }
        if (lane < 8) {
            float v = (lane < 4) ? s[2 * lane] : s[2 * (lane - 4) + 1];
            gsum[warp * 8 + lane] = v;
        }
        __syncthreads();

        if (tid < 16) {
            int uu = tid >> 2, bb = tid & 3;
            float gi = gsum[((0 * 4 + uu) << 2) | bb] + xg[0];
            float gf = gsum[((1 * 4 + uu) << 2) | bb] + xg[1];
            float gg = gsum[((2 * 4 + uu) << 2) | bb] + xg[2];
            float go = gsum[((3 * 4 + uu) << 2) | bb] + xg[3];
            float c = sigf(gf) * csm[tid] + sigf(gi) * tfast(gg);
            csm[tid] = c;
            float h = sigf(go) * tfast(c);
            int u  = u0 + uu;
            size_t bt = (size_t)(bb * T_ + t);
            g_enc[bt * 512 + u] = h;
            bf16 hh = __float2bfloat16(h);
            bf16 hl = __float2bfloat16(h - __bfloat162float(hh));
            g_enc_hi[bt * 512 + u] = hh;
            g_enc_lo[bt * 512 + u] = hl;
            size_t ei = ((size_t)bb * 512 + u) * 1024 + t;
            g_et_hi[ei] = hh;
            g_et_lo[ei] = hl;
            __threadfence();
        }
        __syncthreads();

        if (tid == 0) {
            unsigned a = atomicAdd(&g_cnt[grp * 32], 1u);
            if (a == (unsigned)((t + 1) * 16 - 1)) atomicAdd(&g_root, 1u);
            while (*(volatile unsigned*)&g_root < 8u * (unsigned)(t + 1)) { }
        }
        __syncthreads();
    }
}

// ---------------- LSTM-2: 4 independent warps ----------------
__global__ __launch_bounds__(128)
void k_lstm2(const float* __restrict__ Wp_hh,
             const float* __restrict__ Wmu, const float* __restrict__ bmu,
             const float* __restrict__ Wsig, const float* __restrict__ bsig,
             const int* __restrict__ pad)
{
    __shared__ float wp[1600];
    __shared__ float wmu_s[60];
    __shared__ float wsig_s[20];
    __shared__ float bconst[4];
    __shared__ float hp[4][20];
    __shared__ float gp[4][80];
    __shared__ float tmp[4][4];
    const int tid = threadIdx.x;
    const int b = tid >> 5, lane = tid & 31;

    for (int i = tid; i < 1600; i += 128) wp[i] = Wp_hh[i];
    for (int i = tid; i < 60; i += 128) wmu_s[i] = Wmu[i];
    if (tid < 20) wsig_s[tid] = Wsig[tid];
    if (tid < 3) bconst[tid] = bmu[tid];
    if (tid == 3) bconst[3] = bsig[0];
    if (tid < 80) hp[tid / 20][tid % 20] = 0.f;
    __syncthreads();

    const float invL = 1.f / (float)pad[b];
    float cc = 0.f;
    float mu_prev = 0.f;
    const int r0 = lane, r1 = lane + 32, r2 = lane + 64;
    const int r2c = (r2 < 80) ? r2 : 79;

    float px0 = g_pxw[(size_t)(b * T_) * 128 + r0];
    float px1 = g_pxw[(size_t)(b * T_) * 128 + r1];
    float px2 = (r2 < 80) ? g_pxw[(size_t)(b * T_) * 128 + r2] : 0.f;

    for (int t = 0; t < T_; ++t) {
        float s0 = px0, s1 = px1, s2 = px2;
#pragma unroll
        for (int k = 0; k < 20; ++k) {
            float h = hp[b][k];
            s0 = fmaf(wp[r0 * 20 + k], h, s0);
            s1 = fmaf(wp[r1 * 20 + k], h, s1);
            s2 = fmaf(wp[r2c * 20 + k], h, s2);
        }
        gp[b][r0] = s0;
        gp[b][r1] = s1;
        if (r2 < 80) gp[b][r2] = s2;
        if (t + 1 < T_) {
            size_t base = (size_t)(b * T_ + t + 1) * 128;
            px0 = g_pxw[base + r0];
            px1 = g_pxw[base + r1];
            if (r2 < 80) px2 = g_pxw[base + r2];
        }
        __syncwarp();
        if (lane < 20) {
            float gi = gp[b][lane], gf = gp[b][20 + lane];
            float gg = gp[b][40 + lane], go = gp[b][60 + lane];
            cc = sigf(gf) * cc + sigf(gi) * tfast(gg);
            hp[b][lane] = sigf(go) * tfast(cc);
        }
        __syncwarp();
        if (lane >= 20 && lane < 24) {
            int s = lane - 20;
            const float* wv = (s < 3) ? &wmu_s[s * 20] : wsig_s;
            float acc = bconst[s];
#pragma unroll
            for (int k = 0; k < 20; ++k) acc = fmaf(wv[k], hp[b][k], acc);
            tmp[b][s] = acc;
        }
        __syncwarp();
        if (lane == 0) {
            float m0 = fmaxf(tmp[b][0], 0.f);
            float m1 = fmaxf(tmp[b][1], 0.f);
            float m2 = fmaxf(tmp[b][2], 0.f);
            float sg = sigf(tmp[b][3]);
            float mu = fmaf(m0, mu_prev, (m1 + m2 * (float)(t + 1)) * invL);
            mu_prev = mu;
            g_mu[b * T_ + t]  = mu;
            g_sig[b * T_ + t] = sg;
        }
    }
}

// ---------------- attention weights: compute, normalize, split to bf16 ----------
__global__ __launch_bounds__(256)
void k_wnorm()
{
    __shared__ float wsm[1024];
    __shared__ float red[8];
    const int tid = threadIdx.x, lane = tid & 31, warp = tid >> 5;
    const int bj = blockIdx.x;
    const int b = bj >> 10, j = bj & 1023;
    const float mu = g_mu[bj];
    const float sg = g_sig[bj];
    const float invd  = 1.f / (2.f * sg * sg + 0.001f);
    const float invj1 = 1.f / (float)(j + 1);

    float lsum = 0.f;
#pragma unroll
    for (int i = 0; i < 4; ++i) {
        int t = tid + i * 256;
        float w = 0.f;
        if (t <= j) {
            float r = (float)t * invj1 - mu;
            w = __expf(-r * r * invd);
        }
        wsm[t] = w;
        lsum += w;
    }
    lsum += __shfl_xor_sync(0xffffffffu, lsum, 16);
    lsum += __shfl_xor_sync(0xffffffffu, lsum, 8);
    lsum += __shfl_xor_sync(0xffffffffu, lsum, 4);
    lsum += __shfl_xor_sync(0xffffffffu, lsum, 2);
    lsum += __shfl_xor_sync(0xffffffffu, lsum, 1);
    if (lane == 0) red[warp] = lsum;
    __syncthreads();
    float tot = red[0] + red[1] + red[2] + red[3] + red[4] + red[5] + red[6] + red[7];
    const float scale = 1.f / fmaxf(tot, 1e-12f);

    size_t base = ((size_t)b << 20) + ((size_t)j << 10);
#pragma unroll
    for (int i = 0; i < 4; ++i) {
        int t = tid + i * 256;
        float v = wsm[t] * scale;
        bf16 h = __float2bfloat16(v);
        g_w_hi[base + t] = h;
        g_w_lo[base + t] = __float2bfloat16(v - __bfloat162float(h));
    }
}

// ---------------- launch ----------------
extern "C" void kernel_launch(void* const* d_in, const int* in_sizes, int n_in,
                              void* d_out, int out_size)
{
    const int*   ids      = (const int*)d_in[0];
    const int*   pad      = (const int*)d_in[1];
    const float* emb      = (const float*)d_in[2];
    const float* dec_bias = (const float*)d_in[3];
    const float* Wih      = (const float*)d_in[4];
    const float* Whh      = (const float*)d_in[5];
    const float* bih      = (const float*)d_in[6];
    const float* bhh      = (const float*)d_in[7];
    const float* Wp_ih    = (const float*)d_in[8];
    const float* Wp_hh    = (const float*)d_in[9];
    const float* bp_ih    = (const float*)d_in[10];
    const float* bp_hh    = (const float*)d_in[11];
    const float* Wmu      = (const float*)d_in[12];
    const float* bmu      = (const float*)d_in[13];
    const float* Wsig     = (const float*)d_in[14];
    const float* bsig     = (const float*)d_in[15];
    const float* Wc       = (const float*)d_in[16];
    const float* bc       = (const float*)d_in[17];
    float* out = (float*)d_out;

    float *p_xw, *p_pxw, *p_bp;
    bf16 *p_ehi, *p_elo, *p_whi, *p_wlo, *p_xhi, *p_xlo;
    bf16 *p_nhi, *p_nlo, *p_ethi, *p_etlo, *p_awhi, *p_awlo;
    bf16 *p_cxhi, *p_cxlo, *p_wchi, *p_wclo, *p_wphi, *p_wplo;
    __half *p_ef, *p_cfh;
    cudaGetSymbolAddress((void**)&p_xw,    g_xw);
    cudaGetSymbolAddress((void**)&p_pxw,   g_pxw);
    cudaGetSymbolAddress((void**)&p_bp,    g_bp);
    cudaGetSymbolAddress((void**)&p_ehi,   g_emb_hi);
    cudaGetSymbolAddress((void**)&p_elo,   g_emb_lo);
    cudaGetSymbolAddress((void**)&p_ef,    g_emb_f);
    cudaGetSymbolAddress((void**)&p_whi,   g_wih_hi);
    cudaGetSymbolAddress((void**)&p_wlo,   g_wih_lo);
    cudaGetSymbolAddress((void**)&p_xhi,   g_x_hi);
    cudaGetSymbolAddress((void**)&p_xlo,   g_x_lo);
    cudaGetSymbolAddress((void**)&p_nhi,   g_enc_hi);
    cudaGetSymbolAddress((void**)&p_nlo,   g_enc_lo);
    cudaGetSymbolAddress((void**)&p_ethi,  g_et_hi);
    cudaGetSymbolAddress((void**)&p_etlo,  g_et_lo);
    cudaGetSymbolAddress((void**)&p_awhi,  g_w_hi);
    cudaGetSymbolAddress((void**)&p_awlo,  g_w_lo);
    cudaGetSymbolAddress((void**)&p_cxhi,  g_ctx_hi);
    cudaGetSymbolAddress((void**)&p_cxlo,  g_ctx_lo);
    cudaGetSymbolAddress((void**)&p_cfh,   g_comb_fh);
    cudaGetSymbolAddress((void**)&p_wchi,  g_wc_hi);
    cudaGetSymbolAddress((void**)&p_wclo,  g_wc_lo);
    cudaGetSymbolAddress((void**)&p_wphi,  g_wp_hi);
    cudaGetSymbolAddress((void**)&p_wplo,  g_wp_lo);

    cudaFuncSetAttribute(k_mma, cudaFuncAttributeMaxDynamicSharedMemorySize, MMA_SMEM);
    cudaFuncSetAttribute(k_mma7, cudaFuncAttributeMaxDynamicSharedMemorySize, MMA7_SMEM);

    const int NOB = 1 << 28;

    k_split<<<(V_ * H_ + 255) / 256, 256>>>(emb, p_ehi, p_elo, p_ef, V_ * H_);
    k_split<<<(4 * H_ * H_ + 255) / 256, 256>>>(Wih, p_whi, p_wlo, nullptr, 4 * H_ * H_);
    k_split<<<(H_ * 2 * H_ + 255) / 256, 256>>>(Wc, p_wchi, p_wclo, nullptr, H_ * 2 * H_);
    k_split<<<(80 * H_ + 255) / 256, 256>>>(Wp_ih, p_wphi, p_wplo, nullptr, 80 * H_);
    k_padbias<<<1, 128>>>(bp_ih, bp_hh);
    k_embed_bf<<<(BT * H_ + 255) / 256, 256>>>(ids);

    // K1: xw = x @ Wih^T + bih + bhh -> fp32 [4096, 2048]
    k_mma<<<dim3(16, 32), 256, MMA_SMEM>>>(
        p_xhi, p_xlo, 512, nullptr, nullptr, 0, 8, 8, NOB, 0,
        p_whi, p_wlo, 512, 0, 2048, bih, bhh, p_xw, nullptr, nullptr, 0, 0, 0);

    // K2: LSTM-1 recurrence
    k_lstm1<<<NB1, 256>>>(Whh);

    // K3: pxw = enc @ Wp_ih^T + biases -> fp32 [4096, 128pad]
    k_mma<<<dim3(1, 32), 256, MMA_SMEM>>>(
        p_nhi, p_nlo, 512, nullptr, nullptr, 0, 8, 8, NOB, 0,
        p_wphi, p_wplo, 512, 0, 128, p_bp, nullptr, p_pxw, nullptr, nullptr, 0, 0, 0);

    // K4: LSTM-2 + mu/sigma scan
    k_lstm2<<<1, 128>>>(Wp_hh, Wmu, bmu, Wsig, bsig, pad);

    // K5a: attention weights
    k_wnorm<<<BT, 256>>>();

    // K5b: ctx = w @ enc (batched, triangular skip) -> bf16 hi/lo
    k_mma<<<dim3(4, 32), 256, MMA_SMEM>>>(
        p_awhi, p_awlo, 1024, nullptr, nullptr, 0, 16, 16, 8, (size_t)T_ * T_,
        p_ethi, p_etlo, 1024, (size_t)H_ * T_, 512,
        nullptr, nullptr, nullptr, p_cxhi, p_cxlo, 0, 1, 0);

    // K6: combined = tanh([ctx, enc] @ Wc^T + bc) -> fp16 hi only (for K7)
    k_mma<<<dim3(4, 32), 256, MMA_SMEM>>>(
        p_cxhi, p_cxlo, 512, p_nhi, p_nlo, 512, 8, 16, NOB, 0,
        p_wchi, p_wclo, 1024, 0, 512, bc, nullptr,
        nullptr, (bf16*)p_cfh, nullptr, 1, 0, 1);

    // K7: logits = combined @ emb^T + dec_bias -> fp32 (fp16 single-term)
    k_mma7<<<dim3(32, 250), 256, MMA7_SMEM>>>(
        p_cfh, p_ef, V_, dec_bias, out);
}

// round 17
// speedup vs baseline: 2.5832x; 1.0274x over previous
#include <cuda_runtime.h>
#include <cuda_bf16.h>
#include <cuda_fp16.h>
#include <cstdint>
#include <math.h>

#define B_ 4
#define T_ 1024
#define H_ 512
#define P_ 20
#define V_ 32000
#define BT (B_*T_)
#define NB1 128

typedef __nv_bfloat16 bf16;

// ---------------- scratch (device globals) ----------------
__device__ __align__(256) float g_xw[BT*2048];
__device__ __align__(256) float g_enc[BT*512];
__device__ __align__(256) float g_pxw[BT*128];
__device__ float g_mu[BT];
__device__ float g_sig[BT];
__device__ unsigned g_cnt[256];
__device__ unsigned g_root;
__device__ float g_bp[128];

__device__ __align__(256) __half g_emb_f[V_*H_];
__device__ __align__(256) bf16 g_wih_hi[4*H_*H_];
__device__ __align__(256) bf16 g_wih_lo[4*H_*H_];
__device__ __align__(256) bf16 g_x_hi[BT*H_];
__device__ __align__(256) bf16 g_x_lo[BT*H_];
__device__ __align__(256) bf16 g_enc_hi[BT*H_];
__device__ __align__(256) bf16 g_enc_lo[BT*H_];
__device__ __align__(256) bf16 g_et_hi[B_*H_*T_];
__device__ __align__(256) bf16 g_et_lo[B_*H_*T_];
__device__ __align__(256) bf16 g_w_hi[B_*T_*T_];
__device__ __align__(256) bf16 g_w_lo[B_*T_*T_];
__device__ __align__(256) bf16 g_ctx_hi[BT*H_];
__device__ __align__(256) bf16 g_ctx_lo[BT*H_];
__device__ __align__(256) __half g_comb_fh[BT*H_];
__device__ __align__(256) bf16 g_wc_hi[H_*2*H_];
__device__ __align__(256) bf16 g_wc_lo[H_*2*H_];
__device__ __align__(256) bf16 g_wp_hi[128*H_];
__device__ __align__(256) bf16 g_wp_lo[128*H_];

__device__ __forceinline__ float sigf(float x) { return 1.f / (1.f + __expf(-x)); }
__device__ __forceinline__ float tfast(float x) {
    float a = fabsf(x);
    float e = __expf(2.f * a);
    float t = 1.f - 2.f / (1.f + e);
    return copysignf(t, x);
}

__device__ __forceinline__ uint32_t smem_u32(const void* p) {
    uint32_t a;
    asm("{ .reg .u64 t; cvta.to.shared.u64 t, %1; cvt.u32.u64 %0, t; }"
        : "=r"(a) : "l"(p));
    return a;
}

#define CP_ASYNC16(s, g) \
    asm volatile("cp.async.cg.shared.global [%0], [%1], 16;" :: "r"(s), "l"(g))
#define CP_COMMIT() asm volatile("cp.async.commit_group;" ::: "memory")
#define CP_WAIT1()  asm volatile("cp.async.wait_group 1;" ::: "memory")
#define CP_WAIT0()  asm volatile("cp.async.wait_group 0;" ::: "memory")

#define LDSM4(r0, r1, r2, r3, a)                                             \
    asm volatile("ldmatrix.sync.aligned.m8n8.x4.shared.b16 {%0,%1,%2,%3}, [%4];" \
        : "=r"(r0), "=r"(r1), "=r"(r2), "=r"(r3) : "r"(a))

#define MMA16816(c, A0, A1, A2, A3, B0, B1)                                  \
    asm volatile("mma.sync.aligned.m16n8k16.row.col.f32.bf16.bf16.f32 "      \
        "{%0,%1,%2,%3}, {%4,%5,%6,%7}, {%8,%9}, {%0,%1,%2,%3};"              \
        : "+f"((c)[0]), "+f"((c)[1]), "+f"((c)[2]), "+f"((c)[3])             \
        : "r"(A0), "r"(A1), "r"(A2), "r"(A3), "r"(B0), "r"(B1))

#define MMAF16(c, A0, A1, A2, A3, B0, B1)                                    \
    asm volatile("mma.sync.aligned.m16n8k16.row.col.f32.f16.f16.f32 "        \
        "{%0,%1,%2,%3}, {%4,%5,%6,%7}, {%8,%9}, {%0,%1,%2,%3};"              \
        : "+f"((c)[0]), "+f"((c)[1]), "+f"((c)[2]), "+f"((c)[3])             \
        : "r"(A0), "r"(A1), "r"(A2), "r"(A3), "r"(B0), "r"(B1))

// ---------------- split fp32 -> bf16 hi/lo ----------------
__global__ void k_split(const float* __restrict__ src,
                        bf16* __restrict__ hi, bf16* __restrict__ lo, int n)
{
    int i = blockIdx.x * blockDim.x + threadIdx.x;
    if (i < n) {
        float v = src[i];
        bf16 h = __float2bfloat16(v);
        hi[i] = h;
        lo[i] = __float2bfloat16(v - __bfloat162float(h));
    }
}

// ---------------- fp32 -> fp16 (decoder B) ----------------
__global__ void k_half(const float* __restrict__ src, __half* __restrict__ dst, int n)
{
    int i = blockIdx.x * blockDim.x + threadIdx.x;
    if (i < n) dst[i] = __float2half(src[i]);
}

__global__ void k_padbias(const float* __restrict__ b1, const float* __restrict__ b2)
{
    int i = threadIdx.x;
    if (i < 80) g_bp[i] = b1[i] + b2[i];
}

// ---------------- embedding gather (fp32 src, split on the fly) + counter reset ---
__global__ void k_embed_bf(const int* __restrict__ ids, const float* __restrict__ emb)
{
    if (blockIdx.x == 0) {
        if (threadIdx.x == 0) g_root = 0;
        if (threadIdx.x < 8) g_cnt[threadIdx.x * 32] = 0;
    }
    int i = blockIdx.x * blockDim.x + threadIdx.x;
    if (i < BT * H_) {
        int bt = i >> 9;
        int h  = i & 511;
        float v = emb[(size_t)ids[bt] * H_ + h];
        bf16 hh = __float2bfloat16(v);
        g_x_hi[i] = hh;
        g_x_lo[i] = __float2bfloat16(v - __bfloat162float(hh));
    }
}

// ---------------- generalized bf16x3 HMMA GEMM, 2-stage cp.async (proven) --------
#define MMA_SMEM (2 * 65536)

__global__ __launch_bounds__(256)
void k_mma(const bf16* __restrict__ Ah1, const bf16* __restrict__ Al1, int lda1,
           const bf16* __restrict__ Ah2, const bf16* __restrict__ Al2, int lda2,
           int ksplit, int nchunks, int mbpb, size_t sAbat,
           const bf16* __restrict__ Bh, const bf16* __restrict__ Bl, int ldb, size_t sBbat,
           int N, const float* __restrict__ bias1, const float* __restrict__ bias2,
           float* __restrict__ Cf, bf16* __restrict__ Chi, bf16* __restrict__ Clo,
           int actTanh, int tri, int outHalf)
{
    extern __shared__ char dsm[];
    const uint32_t ub = smem_u32(dsm);
    const int tid = threadIdx.x, lane = tid & 31, wid = tid >> 5;
    const int bm = blockIdx.y, bn = blockIdx.x;
    const int bq = bm / mbpb;
    const int am0 = (bm - bq * mbpb) * 128;
    const bf16* A1h = Ah1 + (size_t)bq * sAbat;
    const bf16* A1l = Al1 + (size_t)bq * sAbat;
    const bf16* Bbh = Bh + (size_t)bq * sBbat;
    const bf16* Bbl = Bl + (size_t)bq * sBbat;

    if (tri) { int need = (am0 >> 6) + 2; if (need < nchunks) nchunks = need; }

    const int wm = (wid >> 2) * 64, wn = (wid & 3) * 32;
    const int aRow = lane & 15, aGrp = lane >> 4;
    const int bRow = (lane & 7) + ((lane >> 4) << 3), bGrp = (lane >> 3) & 1;

    auto issue = [&](int c, int st) {
        uint32_t sb = ub + st * 65536;
#pragma unroll
        for (int i = 0; i < 4; ++i) {
            int idx = i * 256 + tid;
            int row = idx >> 3, seg = idx & 7;
            uint32_t so = sb + (uint32_t)(row * 128 + ((seg ^ (row & 7)) << 4));
            const bf16 *pah, *pal;
            if (c < ksplit) {
                size_t o = (size_t)(am0 + row) * lda1 + c * 64 + seg * 8;
                pah = A1h + o; pal = A1l + o;
            } else {
                size_t o = (size_t)(am0 + row) * lda2 + (c - ksplit) * 64 + seg * 8;
                pah = Ah2 + o; pal = Al2 + o;
            }
            size_t ob = (size_t)(bn * 128 + row) * ldb + c * 64 + seg * 8;
            CP_ASYNC16(so,         pah);
            CP_ASYNC16(so + 16384, pal);
            CP_ASYNC16(so + 32768, Bbh + ob);
            CP_ASYNC16(so + 49152, Bbl + ob);
        }
        CP_COMMIT();
    };

    float acc[4][4][4];
#pragma unroll
    for (int i = 0; i < 4; i++)
#pragma unroll
        for (int j = 0; j < 4; j++)
#pragma unroll
            for (int q = 0; q < 4; q++) acc[i][j][q] = 0.f;

    issue(0, 0);
    for (int c = 0; c < nchunks; ++c) {
        if (c + 1 < nchunks) { issue(c + 1, (c + 1) & 1); CP_WAIT1(); }
        else CP_WAIT0();
        __syncthreads();

        uint32_t uAh = ub + (c & 1) * 65536;
        uint32_t uAl = uAh + 16384, uBh = uAh + 32768, uBl = uAh + 49152;
#pragma unroll
        for (int ks = 0; ks < 4; ++ks) {
            uint32_t bh[8], bl[8];
#pragma unroll
            for (int h = 0; h < 2; ++h) {
                int row = wn + h * 16 + bRow;
                int grp = 2 * ks + bGrp;
                uint32_t off = (uint32_t)(row * 128 + ((grp ^ (row & 7)) << 4));
                LDSM4(bh[h*4+0], bh[h*4+1], bh[h*4+2], bh[h*4+3], uBh + off);
                LDSM4(bl[h*4+0], bl[h*4+1], bl[h*4+2], bl[h*4+3], uBl + off);
            }
#pragma unroll
            for (int mi = 0; mi < 4; ++mi) {
                int row = wm + mi * 16 + aRow;
                int grp = 2 * ks + aGrp;
                uint32_t off = (uint32_t)(row * 128 + ((grp ^ (row & 7)) << 4));
                uint32_t ah[4], al[4];
                LDSM4(ah[0], ah[1], ah[2], ah[3], uAh + off);
                LDSM4(al[0], al[1], al[2], al[3], uAl + off);
#pragma unroll
                for (int ni = 0; ni < 4; ++ni) {
                    int bx = (ni >> 1) * 4 + (ni & 1) * 2;
                    MMA16816(acc[mi][ni], ah[0], ah[1], ah[2], ah[3], bh[bx], bh[bx+1]);
                    MMA16816(acc[mi][ni], ah[0], ah[1], ah[2], ah[3], bl[bx], bl[bx+1]);
                    MMA16816(acc[mi][ni], al[0], al[1], al[2], al[3], bh[bx], bh[bx+1]);
                }
            }
        }
        __syncthreads();
    }

    // epilogue
#pragma unroll
    for (int mi = 0; mi < 4; ++mi) {
#pragma unroll
        for (int ni = 0; ni < 4; ++ni) {
            int row = bm * 128 + wm + mi * 16 + (lane >> 2);
            int col = bn * 128 + wn + ni * 8 + ((lane & 3) << 1);
            float b0 = 0.f, b1 = 0.f;
            if (bias1) { b0 = bias1[col]; b1 = bias1[col + 1]; }
            if (bias2) { b0 += bias2[col]; b1 += bias2[col + 1]; }
            float v00 = acc[mi][ni][0] + b0, v01 = acc[mi][ni][1] + b1;
            float v10 = acc[mi][ni][2] + b0, v11 = acc[mi][ni][3] + b1;
            if (actTanh) {
                v00 = tfast(v00); v01 = tfast(v01);
                v10 = tfast(v10); v11 = tfast(v11);
            }
            size_t i0 = (size_t)row * N + col;
            size_t i1 = (size_t)(row + 8) * N + col;
            if (Cf) {
                *(float2*)&Cf[i0] = make_float2(v00, v01);
                *(float2*)&Cf[i1] = make_float2(v10, v11);
            }
            if (Chi) {
                if (outHalf) {
                    __half* H = (__half*)Chi;
                    __half2 p;
                    p.x = __float2half(v00); p.y = __float2half(v01);
                    *(__half2*)&H[i0] = p;
                    p.x = __float2half(v10); p.y = __float2half(v11);
                    *(__half2*)&H[i1] = p;
                } else {
                    bf16 h00 = __float2bfloat16(v00), h01 = __float2bfloat16(v01);
                    bf16 h10 = __float2bfloat16(v10), h11 = __float2bfloat16(v11);
                    __nv_bfloat162 p;
                    p.x = h00; p.y = h01; *(__nv_bfloat162*)&Chi[i0] = p;
                    p.x = h10; p.y = h11; *(__nv_bfloat162*)&Chi[i1] = p;
                    if (Clo) {
                        p.x = __float2bfloat16(v00 - __bfloat162float(h00));
                        p.y = __float2bfloat16(v01 - __bfloat162float(h01));
                        *(__nv_bfloat162*)&Clo[i0] = p;
                        p.x = __float2bfloat16(v10 - __bfloat162float(h10));
                        p.y = __float2bfloat16(v11 - __bfloat162float(h11));
                        *(__nv_bfloat162*)&Clo[i1] = p;
                    }
                }
            }
        }
    }
}

// ---------------- K7 decoder: fp16 single-term GEMM, 2 CTAs/SM ----------------
#define MMA7_SMEM (2 * 32768)

__global__ __launch_bounds__(256, 2)
void k_mma7(const __half* __restrict__ Ah, const __half* __restrict__ Bh, int N,
            const float* __restrict__ bias, float* __restrict__ Cf)
{
    extern __shared__ char dsm[];
    const uint32_t ub = smem_u32(dsm);
    const int tid = threadIdx.x, lane = tid & 31, wid = tid >> 5;
    const int bm = blockIdx.x, bn = blockIdx.y;
    const int wm = (wid >> 2) * 64, wn = (wid & 3) * 32;
    const int aRow = lane & 15, aGrp = lane >> 4;
    const int bRow = (lane & 7) + ((lane >> 4) << 3), bGrp = (lane >> 3) & 1;

    auto issue = [&](int c, int st) {
        uint32_t sb = ub + st * 32768;
#pragma unroll
        for (int i = 0; i < 4; ++i) {
            int idx = i * 256 + tid;
            int row = idx >> 3, seg = idx & 7;
            uint32_t so = sb + (uint32_t)(row * 128 + ((seg ^ (row & 7)) << 4));
            size_t oa = (size_t)(bm * 128 + row) * 512 + c * 64 + seg * 8;
            size_t ob = (size_t)(bn * 128 + row) * 512 + c * 64 + seg * 8;
            CP_ASYNC16(so,         Ah + oa);
            CP_ASYNC16(so + 16384, Bh + ob);
        }
        CP_COMMIT();
    };

    float acc[4][4][4];
#pragma unroll
    for (int i = 0; i < 4; i++)
#pragma unroll
        for (int j = 0; j < 4; j++)
#pragma unroll
            for (int q = 0; q < 4; q++) acc[i][j][q] = 0.f;

    issue(0, 0);
    for (int c = 0; c < 8; ++c) {
        if (c + 1 < 8) { issue(c + 1, (c + 1) & 1); CP_WAIT1(); }
        else CP_WAIT0();
        __syncthreads();

        uint32_t uA = ub + (c & 1) * 32768;
        uint32_t uB = uA + 16384;
#pragma unroll
        for (int ks = 0; ks < 4; ++ks) {
            uint32_t bh[8];
#pragma unroll
            for (int h = 0; h < 2; ++h) {
                int row = wn + h * 16 + bRow;
                int grp = 2 * ks + bGrp;
                uint32_t off = (uint32_t)(row * 128 + ((grp ^ (row & 7)) << 4));
                LDSM4(bh[h*4+0], bh[h*4+1], bh[h*4+2], bh[h*4+3], uB + off);
            }
#pragma unroll
            for (int mi = 0; mi < 4; ++mi) {
                int row = wm + mi * 16 + aRow;
                int grp = 2 * ks + aGrp;
                uint32_t off = (uint32_t)(row * 128 + ((grp ^ (row & 7)) << 4));
                uint32_t ah[4];
                LDSM4(ah[0], ah[1], ah[2], ah[3], uA + off);
#pragma unroll
                for (int ni = 0; ni < 4; ++ni) {
                    int bx = (ni >> 1) * 4 + (ni & 1) * 2;
                    MMAF16(acc[mi][ni], ah[0], ah[1], ah[2], ah[3], bh[bx], bh[bx+1]);
                }
            }
        }
        __syncthreads();
    }

#pragma unroll
    for (int mi = 0; mi < 4; ++mi) {
#pragma unroll
        for (int ni = 0; ni < 4; ++ni) {
            int row = bm * 128 + wm + mi * 16 + (lane >> 2);
            int col = bn * 128 + wn + ni * 8 + ((lane & 3) << 1);
            float b0 = bias[col], b1 = bias[col + 1];
            size_t i0 = (size_t)row * N + col;
            size_t i1 = (size_t)(row + 8) * N + col;
            *(float2*)&Cf[i0] = make_float2(acc[mi][ni][0] + b0, acc[mi][ni][1] + b1);
            *(float2*)&Cf[i1] = make_float2(acc[mi][ni][2] + b0, acc[mi][ni][3] + b1);
        }
    }
}

// ---------------- LSTM-1 persistent kernel (R11-proven atomic barrier; FROZEN) ------
__global__ __launch_bounds__(256)
void k_lstm1(const float* __restrict__ Whh)
{
    __shared__ float hsm[2048];
    __shared__ float gsum[64];
    __shared__ float csm[16];
    const int tid  = threadIdx.x;
    const int u0   = blockIdx.x * 4;
    const int warp = tid >> 5, lane = tid & 31;
    const int grp  = blockIdx.x >> 4;

    const int r0 = 2 * warp, r1 = 2 * warp + 1;
    const float* W0 = Whh + ((size_t)((r0 >> 2) * 512 + u0 + (r0 & 3))) * 512;
    const float* W1 = Whh + ((size_t)((r1 >> 2) * 512 + u0 + (r1 & 3))) * 512;
    float4 w0[4], w1[4];
#pragma unroll
    for (int q = 0; q < 4; ++q) {
        w0[q] = *(const float4*)(W0 + 4 * lane + 128 * q);
        w1[q] = *(const float4*)(W1 + 4 * lane + 128 * q);
    }
    if (tid < 16) csm[tid] = 0.f;
    __syncthreads();

    for (int t = 0; t < T_; ++t) {
        float xg[4];
        if (tid < 16) {
            int uu = tid >> 2, b = tid & 3;
            const float* xr = g_xw + (size_t)(b * T_ + t) * 2048 + u0 + uu;
            xg[0] = xr[0]; xg[1] = xr[512]; xg[2] = xr[1024]; xg[3] = xr[1536];
        }
        if (t > 0) {
            for (int i = tid; i < 512; i += 256) {
                int b = i >> 7, k4 = i & 127;
                ((float4*)hsm)[i] =
                    ((const float4*)(g_enc + (size_t)(b * T_ + t - 1) * 512))[k4];
            }
        } else {
            for (int i = tid; i < 2048; i += 256) hsm[i] = 0.f;
        }
        __syncthreads();

        float s[8];
#pragma unroll
        for (int b = 0; b < 4; ++b) {
            const float* hb = hsm + b * 512 + 4 * lane;
            float4 h0 = *(const float4*)(hb);
            float4 h1 = *(const float4*)(hb + 128);
            float4 h2 = *(const float4*)(hb + 256);
            float4 h3 = *(const float4*)(hb + 384);
            float a0, a1;
            a0 = w0[0].x*h0.x + w0[0].y*h0.y + w0[0].z*h0.z + w0[0].w*h0.w;
            a0 += w0[1].x*h1.x + w0[1].y*h1.y + w0[1].z*h1.z + w0[1].w*h1.w;
            a0 += w0[2].x*h2.x + w0[2].y*h2.y + w0[2].z*h2.z + w0[2].w*h2.w;
            a0 += w0[3].x*h3.x + w0[3].y*h3.y + w0[3].z*h3.z + w0[3].w*h3.w;
            a1 = w1[0].x*h0.x + w1[0].y*h0.y + w1[0].z*h0.z + w1[0].w*h0.w;
            a1 += w1[1].x*h1.x + w1[1].y*h1.y + w1[1].z*h1.z + w1[1].w*h1.w;
            a1 += w1[2].x*h2.x + w1[2].y*h2.y + w1[2].z*h2.z + w1[2].w*h2.w;
            a1 += w1[3].x*h3.x + w1[3].y*h3.y + w1[3].z*h3.z + w1[3].w*h3.w;
            s[b * 2] = a0; s[b * 2 + 1] = a1;
        }
#pragma unroll
        for (int i = 0; i < 8; ++i) {
            s[i] += __shfl_xor_sync(0xffffffffu, s[i], 16);
            s[i] += __shfl_xor_sync(0xffffffffu, s[i], 8);
            s[i] += __shfl_xor_sync(0xffffffffu, s[i], 4);
            s[i] += __shfl_xor_sync(0xffffffffu, s[i], 2);
            s[i] += __shfl_xor_sync(0xffffffffu, s[i], 1);
        }
        if (lane < 8) {
            float v = (lane < 4) ? s[2 * lane] : s[2 * (lane - 4) + 1];
            gsum[warp * 8 + lane] = v;
        }
        __syncthreads();

        if (tid < 16) {
            int uu = tid >> 2, bb = tid & 3;
            float gi = gsum[((0 * 4 + uu) << 2) | bb] + xg[0];
            float gf = gsum[((1 * 4 + uu) << 2) | bb] + xg[1];
            float gg = gsum[((2 * 4 + uu) << 2) | bb] + xg[2];
            float go = gsum[((3 * 4 + uu) << 2) | bb] + xg[3];
            float c = sigf(gf) * csm[tid] + sigf(gi) * tfast(gg);
            csm[tid] = c;
            float h = sigf(go) * tfast(c);
            int u  = u0 + uu;
            size_t bt = (size_t)(bb * T_ + t);
            g_enc[bt * 512 + u] = h;
            bf16 hh = __float2bfloat16(h);
            bf16 hl = __float2bfloat16(h - __bfloat162float(hh));
            g_enc_hi[bt * 512 + u] = hh;
            g_enc_lo[bt * 512 + u] = hl;
            size_t ei = ((size_t)bb * 512 + u) * 1024 + t;
            g_et_hi[ei] = hh;
            g_et_lo[ei] = hl;
            __threadfence();
        }
        __syncthreads();

        if (tid == 0) {
            unsigned a = atomicAdd(&g_cnt[grp * 32], 1u);
            if (a == (unsigned)((t + 1) * 16 - 1)) atomicAdd(&g_root, 1u);
            while (*(volatile unsigned*)&g_root < 8u * (unsigned)(t + 1)) { }
        }
        __syncthreads();
    }
}

// ---------------- LSTM-2: 4 warps, register-resident weights ----------------
__global__ __launch_bounds__(128)
void k_lstm2(const float* __restrict__ Wp_hh,
             const float* __restrict__ Wmu, const float* __restrict__ bmu,
             const float* __restrict__ Wsig, const float* __restrict__ bsig,
             const int* __restrict__ pad)
{
    __shared__ float wmu_s[60];
    __shared__ float wsig_s[20];
    __shared__ float bconst[4];
    __shared__ float hp[4][20];
    __shared__ float gp[4][80];
    __shared__ float tmp[4][4];
    const int tid = threadIdx.x;
    const int b = tid >> 5, lane = tid & 31;

    for (int i = tid; i < 60; i += 128) wmu_s[i] = Wmu[i];
    if (tid < 20) wsig_s[tid] = Wsig[tid];
    if (tid < 3) bconst[tid] = bmu[tid];
    if (tid == 3) bconst[3] = bsig[0];
    if (tid < 80) hp[tid / 20][tid % 20] = 0.f;

    const int r0 = lane, r1 = lane + 32, r2 = lane + 64;
    const int r2c = (r2 < 80) ? r2 : 79;
    // register-resident weight rows (3 x 20 floats per lane)
    float wr0[20], wr1[20], wr2[20];
#pragma unroll
    for (int k = 0; k < 20; ++k) {
        wr0[k] = Wp_hh[r0 * 20 + k];
        wr1[k] = Wp_hh[r1 * 20 + k];
        wr2[k] = Wp_hh[r2c * 20 + k];
    }
    __syncthreads();

    const float invL = 1.f / (float)pad[b];
    float cc = 0.f;
    float mu_prev = 0.f;

    float px0 = g_pxw[(size_t)(b * T_) * 128 + r0];
    float px1 = g_pxw[(size_t)(b * T_) * 128 + r1];
    float px2 = (r2 < 80) ? g_pxw[(size_t)(b * T_) * 128 + r2] : 0.f;

    for (int t = 0; t < T_; ++t) {
        float s0 = px0, s1 = px1, s2 = px2;
#pragma unroll
        for (int k = 0; k < 20; ++k) {
            float h = hp[b][k];
            s0 = fmaf(wr0[k], h, s0);
            s1 = fmaf(wr1[k], h, s1);
            s2 = fmaf(wr2[k], h, s2);
        }
        gp[b][r0] = s0;
        gp[b][r1] = s1;
        if (r2 < 80) gp[b][r2] = s2;
        if (t + 1 < T_) {
            size_t base = (size_t)(b * T_ + t + 1) * 128;
            px0 = g_pxw[base + r0];
            px1 = g_pxw[base + r1];
            if (r2 < 80) px2 = g_pxw[base + r2];
        }
        __syncwarp();
        if (lane < 20) {
            float gi = gp[b][lane], gf = gp[b][20 + lane];
            float gg = gp[b][40 + lane], go = gp[b][60 + lane];
            cc = sigf(gf) * cc + sigf(gi) * tfast(gg);
            hp[b][lane] = sigf(go) * tfast(cc);
        }
        __syncwarp();
        if (lane >= 20 && lane < 24) {
            int s = lane - 20;
            const float* wv = (s < 3) ? &wmu_s[s * 20] : wsig_s;
            float acc = bconst[s];
#pragma unroll
            for (int k = 0; k < 20; ++k) acc = fmaf(wv[k], hp[b][k], acc);
            tmp[b][s] = acc;
        }
        __syncwarp();
        if (lane == 0) {
            float m0 = fmaxf(tmp[b][0], 0.f);
            float m1 = fmaxf(tmp[b][1], 0.f);
            float m2 = fmaxf(tmp[b][2], 0.f);
            float sg = sigf(tmp[b][3]);
            float mu = fmaf(m0, mu_prev, (m1 + m2 * (float)(t + 1)) * invL);
            mu_prev = mu;
            g_mu[b * T_ + t]  = mu;
            g_sig[b * T_ + t] = sg;
        }
    }
}

// ---------------- attention weights: normalize, split, capped stores ----------
__global__ __launch_bounds__(256)
void k_wnorm()
{
    __shared__ float wsm[1024];
    __shared__ float red[8];
    const int tid = threadIdx.x, lane = tid & 31, warp = tid >> 5;
    const int bj = blockIdx.x;
    const int b = bj >> 10, j = bj & 1023;
    const float mu = g_mu[bj];
    const float sg = g_sig[bj];
    const float invd  = 1.f / (2.f * sg * sg + 0.001f);
    const float invj1 = 1.f / (float)(j + 1);

    float lsum = 0.f;
#pragma unroll
    for (int i = 0; i < 4; ++i) {
        int t = tid + i * 256;
        float w = 0.f;
        if (t <= j) {
            float r = (float)t * invj1 - mu;
            w = __expf(-r * r * invd);
        }
        wsm[t] = w;
        lsum += w;
    }
    lsum += __shfl_xor_sync(0xffffffffu, lsum, 16);
    lsum += __shfl_xor_sync(0xffffffffu, lsum, 8);
    lsum += __shfl_xor_sync(0xffffffffu, lsum, 4);
    lsum += __shfl_xor_sync(0xffffffffu, lsum, 2);
    lsum += __shfl_xor_sync(0xffffffffu, lsum, 1);
    if (lane == 0) red[warp] = lsum;
    __syncthreads();
    float tot = red[0] + red[1] + red[2] + red[3] + red[4] + red[5] + red[6] + red[7];
    const float scale = 1.f / fmaxf(tot, 1e-12f);

    // K5b's triangular skip only reads t < (j/128 + 1)*128 — cap stores there
    const int tmax = ((j >> 7) + 1) << 7;
    size_t base = ((size_t)b << 20) + ((size_t)j << 10);
#pragma unroll
    for (int i = 0; i < 4; ++i) {
        int t = tid + i * 256;
        if (t < tmax) {
            float v = wsm[t] * scale;
            bf16 h = __float2bfloat16(v);
            g_w_hi[base + t] = h;
            g_w_lo[base + t] = __float2bfloat16(v - __bfloat162float(h));
        }
    }
}

// ---------------- launch ----------------
extern "C" void kernel_launch(void* const* d_in, const int* in_sizes, int n_in,
                              void* d_out, int out_size)
{
    const int*   ids      = (const int*)d_in[0];
    const int*   pad      = (const int*)d_in[1];
    const float* emb      = (const float*)d_in[2];
    const float* dec_bias = (const float*)d_in[3];
    const float* Wih      = (const float*)d_in[4];
    const float* Whh      = (const float*)d_in[5];
    const float* bih      = (const float*)d_in[6];
    const float* bhh      = (const float*)d_in[7];
    const float* Wp_ih    = (const float*)d_in[8];
    const float* Wp_hh    = (const float*)d_in[9];
    const float* bp_ih    = (const float*)d_in[10];
    const float* bp_hh    = (const float*)d_in[11];
    const float* Wmu      = (const float*)d_in[12];
    const float* bmu      = (const float*)d_in[13];
    const float* Wsig     = (const float*)d_in[14];
    const float* bsig     = (const float*)d_in[15];
    const float* Wc       = (const float*)d_in[16];
    const float* bc       = (const float*)d_in[17];
    float* out = (float*)d_out;

    float *p_xw, *p_pxw, *p_bp;
    bf16 *p_whi, *p_wlo, *p_xhi, *p_xlo;
    bf16 *p_nhi, *p_nlo, *p_ethi, *p_etlo, *p_awhi, *p_awlo;
    bf16 *p_cxhi, *p_cxlo, *p_wchi, *p_wclo, *p_wphi, *p_wplo;
    __half *p_ef, *p_cfh;
    cudaGetSymbolAddress((void**)&p_xw,    g_xw);
    cudaGetSymbolAddress((void**)&p_pxw,   g_pxw);
    cudaGetSymbolAddress((void**)&p_bp,    g_bp);
    cudaGetSymbolAddress((void**)&p_ef,    g_emb_f);
    cudaGetSymbolAddress((void**)&p_whi,   g_wih_hi);
    cudaGetSymbolAddress((void**)&p_wlo,   g_wih_lo);
    cudaGetSymbolAddress((void**)&p_xhi,   g_x_hi);
    cudaGetSymbolAddress((void**)&p_xlo,   g_x_lo);
    cudaGetSymbolAddress((void**)&p_nhi,   g_enc_hi);
    cudaGetSymbolAddress((void**)&p_nlo,   g_enc_lo);
    cudaGetSymbolAddress((void**)&p_ethi,  g_et_hi);
    cudaGetSymbolAddress((void**)&p_etlo,  g_et_lo);
    cudaGetSymbolAddress((void**)&p_awhi,  g_w_hi);
    cudaGetSymbolAddress((void**)&p_awlo,  g_w_lo);
    cudaGetSymbolAddress((void**)&p_cxhi,  g_ctx_hi);
    cudaGetSymbolAddress((void**)&p_cxlo,  g_ctx_lo);
    cudaGetSymbolAddress((void**)&p_cfh,   g_comb_fh);
    cudaGetSymbolAddress((void**)&p_wchi,  g_wc_hi);
    cudaGetSymbolAddress((void**)&p_wclo,  g_wc_lo);
    cudaGetSymbolAddress((void**)&p_wphi,  g_wp_hi);
    cudaGetSymbolAddress((void**)&p_wplo,  g_wp_lo);

    cudaFuncSetAttribute(k_mma, cudaFuncAttributeMaxDynamicSharedMemorySize, MMA_SMEM);
    cudaFuncSetAttribute(k_mma7, cudaFuncAttributeMaxDynamicSharedMemorySize, MMA7_SMEM);

    const int NOB = 1 << 28;

    k_half<<<(V_ * H_ + 255) / 256, 256>>>(emb, p_ef, V_ * H_);
    k_split<<<(4 * H_ * H_ + 255) / 256, 256>>>(Wih, p_whi, p_wlo, 4 * H_ * H_);
    k_split<<<(H_ * 2 * H_ + 255) / 256, 256>>>(Wc, p_wchi, p_wclo, H_ * 2 * H_);
    k_split<<<(80 * H_ + 255) / 256, 256>>>(Wp_ih, p_wphi, p_wplo, 80 * H_);
    k_padbias<<<1, 128>>>(bp_ih, bp_hh);
    k_embed_bf<<<(BT * H_ + 255) / 256, 256>>>(ids, emb);

    // K1: xw = x @ Wih^T + bih + bhh -> fp32 [4096, 2048]
    k_mma<<<dim3(16, 32), 256, MMA_SMEM>>>(
        p_xhi, p_xlo, 512, nullptr, nullptr, 0, 8, 8, NOB, 0,
        p_whi, p_wlo, 512, 0, 2048, bih, bhh, p_xw, nullptr, nullptr, 0, 0, 0);

    // K2: LSTM-1 recurrence
    k_lstm1<<<NB1, 256>>>(Whh);

    // K3: pxw = enc @ Wp_ih^T + biases -> fp32 [4096, 128pad]
    k_mma<<<dim3(1, 32), 256, MMA_SMEM>>>(
        p_nhi, p_nlo, 512, nullptr, nullptr, 0, 8, 8, NOB, 0,
        p_wphi, p_wplo, 512, 0, 128, p_bp, nullptr, p_pxw, nullptr, nullptr, 0, 0, 0);

    // K4: LSTM-2 + mu/sigma scan
    k_lstm2<<<1, 128>>>(Wp_hh, Wmu, bmu, Wsig, bsig, pad);

    // K5a: attention weights
    k_wnorm<<<BT, 256>>>();

    // K5b: ctx = w @ enc (batched, triangular skip) -> bf16 hi/lo
    k_mma<<<dim3(4, 32), 256, MMA_SMEM>>>(
        p_awhi, p_awlo, 1024, nullptr, nullptr, 0, 16, 16, 8, (size_t)T_ * T_,
        p_ethi, p_etlo, 1024, (size_t)H_ * T_, 512,
        nullptr, nullptr, nullptr, p_cxhi, p_cxlo, 0, 1, 0);

    // K6: combined = tanh([ctx, enc] @ Wc^T + bc) -> fp16 hi only (for K7)
    k_mma<<<dim3(4, 32), 256, MMA_SMEM>>>(
        p_cxhi, p_cxlo, 512, p_nhi, p_nlo, 512, 8, 16, NOB, 0,
        p_wchi, p_wclo, 1024, 0, 512, bc, nullptr,
        nullptr, (bf16*)p_cfh, nullptr, 1, 0, 1);

    // K7: logits = combined @ emb^T + dec_bias -> fp32 (fp16 single-term, 2 CTA/SM)
    k_mma7<<<dim3(32, 250), 256, MMA7_SMEM>>>(
        p_cfh, p_ef, V_, dec_bias, out);
}